// round 13
// baseline (speedup 1.0000x reference)
#include <cuda_runtime.h>
#include <math.h>

// ---------------- static scratch ----------------
#define NSP 524288            // 32*32*32*16 points per (b,c)
#define NCH 20
#define NB  2
#define NMODE 24576           // 16*16*16*6 kept modes

__device__ float  g_hA[NB*NCH*NSP];          // 84 MB
__device__ float  g_hB[NB*NCH*NSP];          // 84 MB
__device__ float2 g_fa[NB*NCH*96*1024];      // S1 [bc][kz*6+kt][x*32+y]
__device__ float2 g_fb[NB*1024*1920];        // S2 [b][y*32+z][o*96 + kx*6+kt]  (yz-major)
__device__ float2 g_fd[NB*NCH*NMODE];        // x_ft  (m = (kx*16+ky)*96 + kz*6+kt)
__device__ float2 g_fe[NB*NCH*NMODE];        // out_ft SLAB-MAJOR: [(kx*6+kt)*256 + ky*16+kz]

// cos(pi*j/16); sin(pi*j/16) = CSX[(j+24)&31]
__device__ static const float CSX[32] = {
     1.000000000f,  0.980785280f,  0.923879533f,  0.831469612f,
     0.707106781f,  0.555570233f,  0.382683432f,  0.195090322f,
     0.000000000f, -0.195090322f, -0.382683432f, -0.555570233f,
    -0.707106781f, -0.831469612f, -0.923879533f, -0.980785280f,
    -1.000000000f, -0.980785280f, -0.923879533f, -0.831469612f,
    -0.707106781f, -0.555570233f, -0.382683432f, -0.195090322f,
     0.000000000f,  0.195090322f,  0.382683432f,  0.555570233f,
     0.707106781f,  0.831469612f,  0.923879533f,  0.980785280f };

#define CSI(p) CSX[(p) & 31]
#define SNI(p) CSX[((p) + 24) & 31]
#define KOF(m) ((m) + ((m) >= 8 ? 16 : 0))

__device__ float2 d_invT[96];   // [t(16)][k(6)] ((k==0?1:2)/16)*(cos,sin)(+2pi k t/16)

__device__ __forceinline__ float gelu_exact(float v) {
    return 0.5f * v * (1.0f + erff(v * 0.70710678118654752f));
}

__global__ void k_init() {
    int tid = threadIdx.x;
    if (tid < 96) {
        int t2 = tid / 6, k2 = tid % 6;
        int ph2 = (k2 * t2) & 15;
        float wk = (k2 == 0 ? 1.0f : 2.0f) * (1.0f/16.0f);
        float s2, c2; sincospif((float)ph2 / 8.0f, &s2, &c2);
        d_invT[tid] = make_float2(wk * c2, wk * s2);
    }
}

// ---------------- lift ------------------------------------------------------
__global__ void __launch_bounds__(256) k_lift(const float* __restrict__ x,
                                              const float* __restrict__ w,
                                              const float* __restrict__ bias) {
    int tid = blockIdx.x * blockDim.x + threadIdx.x;
    if (tid >= NB * NSP) return;
    int b = tid / NSP, p = tid % NSP;
    float xi[5];
#pragma unroll
    for (int i = 0; i < 5; i++) xi[i] = x[(size_t)tid * 5 + i];
#pragma unroll
    for (int c = 0; c < NCH; c++) {
        float a = __ldg(&bias[c]);
#pragma unroll
        for (int i = 0; i < 5; i++) a += xi[i] * __ldg(&w[i * NCH + c]);
        g_hA[(size_t)(b * NCH + c) * NSP + p] = a;
    }
}

// ---------------- fwd T (16->6) + Z (32->16), radix-2 imm -------------------
__global__ void __launch_bounds__(128) k_fwdTZ(int src) {
    __shared__ float2 st[6 * 16 * 33];            // [kt][yl][z] pad 33
    const float* h = src ? g_hB : g_hA;
    int bid = blockIdx.x;
    int yh = bid & 1, x = (bid >> 1) & 31, bc = bid >> 6;
    int tid = threadIdx.x;

#pragma unroll
    for (int q = 0; q < 4; q++) {
        int p = q * 128 + tid;
        int yl = p >> 5, z = p & 31;
        const float4* src4 = (const float4*)(h + (size_t)bc * NSP + x * 16384
                                             + (yh * 16 + yl) * 512 + z * 16);
        float v[16];
#pragma unroll
        for (int r = 0; r < 4; r++) {
            float4 f = src4[r];
            v[r*4+0]=f.x; v[r*4+1]=f.y; v[r*4+2]=f.z; v[r*4+3]=f.w;
        }
        float ue[8], uo[8];
#pragma unroll
        for (int t = 0; t < 8; t++) { ue[t] = v[t] + v[t+8]; uo[t] = v[t] - v[t+8]; }
#pragma unroll
        for (int k = 0; k < 6; k++) {
            const float* wsrc = (k & 1) ? uo : ue;
            float ax = 0.f, ay = 0.f;
#pragma unroll
            for (int t = 0; t < 8; t++) {
                ax += wsrc[t] * CSI(2*k*t);
                ay -= wsrc[t] * SNI(2*k*t);
            }
            st[(k * 16 + yl) * 33 + z] = make_float2(ax, ay);
        }
    }
    __syncthreads();

    // stage Z: 96 threads = (kt 6, yl 16); radix-2, 16 accs
    if (tid < 96) {
        int kt = tid >> 4, yl = tid & 15;
        float2 A[16];
#pragma unroll
        for (int m = 0; m < 16; m++) A[m] = make_float2(0.f, 0.f);
#pragma unroll
        for (int zp = 0; zp < 16; zp++) {
            float2 g0 = st[(kt * 16 + yl) * 33 + zp];
            float2 g1 = st[(kt * 16 + yl) * 33 + zp + 16];
            float2 u = make_float2(g0.x + g1.x, g0.y + g1.y);
            float2 v = make_float2(g0.x - g1.x, g0.y - g1.y);
#pragma unroll
            for (int mm = 0; mm < 8; mm++) {
                const int ke = KOF(2*mm);
                A[2*mm].x   += u.x * CSI(ke*zp) + u.y * SNI(ke*zp);
                A[2*mm].y   += u.y * CSI(ke*zp) - u.x * SNI(ke*zp);
                const int ko = KOF(2*mm+1);
                A[2*mm+1].x += v.x * CSI(ko*zp) + v.y * SNI(ko*zp);
                A[2*mm+1].y += v.y * CSI(ko*zp) - v.x * SNI(ko*zp);
            }
        }
#pragma unroll
        for (int m = 0; m < 16; m++)
            g_fa[((size_t)bc * 96 + m * 6 + kt) * 1024 + x * 32 + yh * 16 + yl] = A[m];
    }
}

// ---------------- fwd Y + X, radix-2 imm, 4 slabs / 128 threads -------------
__global__ void __launch_bounds__(128) k_fwdYX() {
    __shared__ float2 P[4 * 32 * 33];   // [s][x][y] pad 33; reused as OUT[1024]
    int bid = blockIdx.x;
    int sp = bid % 24, bc = bid / 24;
    int tid = threadIdx.x;
    const float2* s1 = g_fa + ((size_t)bc * 96 + sp * 4) * 1024;
#pragma unroll
    for (int q = 0; q < 32; q++) {
        int u = q * 128 + tid;
        int s = u >> 10, r = u & 1023;
        P[s * 1056 + (r >> 5) * 33 + (r & 31)] = s1[u];
    }
    __syncthreads();

    // stage Y: (s 4, x 32) = 128; radix-2 over y, 16 ky accs; in-place write
    {
        int s = tid >> 5, x = tid & 31;
        float2 A[16];
#pragma unroll
        for (int m = 0; m < 16; m++) A[m] = make_float2(0.f, 0.f);
#pragma unroll
        for (int yp = 0; yp < 16; yp++) {
            float2 g0 = P[s * 1056 + x * 33 + yp];
            float2 g1 = P[s * 1056 + x * 33 + yp + 16];
            float2 u = make_float2(g0.x + g1.x, g0.y + g1.y);
            float2 v = make_float2(g0.x - g1.x, g0.y - g1.y);
#pragma unroll
            for (int mm = 0; mm < 8; mm++) {
                const int ke = KOF(2*mm);
                A[2*mm].x   += u.x * CSI(ke*yp) + u.y * SNI(ke*yp);
                A[2*mm].y   += u.y * CSI(ke*yp) - u.x * SNI(ke*yp);
                const int ko = KOF(2*mm+1);
                A[2*mm+1].x += v.x * CSI(ko*yp) + v.y * SNI(ko*yp);
                A[2*mm+1].y += v.y * CSI(ko*yp) - v.x * SNI(ko*yp);
            }
        }
#pragma unroll
        for (int m = 0; m < 16; m++) P[s * 1056 + x * 33 + m] = A[m];
    }
    __syncthreads();

    // stage X: (s 4, ky 16, par 2) = 128; mode-parity split with twiddle fold
    {
        int s = tid >> 5;
        int r = tid & 31; int ky = r >> 1; int par = r & 1;
        float2 A[8];
#pragma unroll
        for (int mm = 0; mm < 8; mm++) A[mm] = make_float2(0.f, 0.f);
#pragma unroll
        for (int xp = 0; xp < 16; xp++) {
            float2 g0 = P[s * 1056 + xp * 33 + ky];
            float2 g1 = P[s * 1056 + (xp + 16) * 33 + ky];
            float2 w;
            if (par) {
                float vx = g0.x - g1.x, vy = g0.y - g1.y;
                w.x = vx * CSI(xp) + vy * SNI(xp);
                w.y = vy * CSI(xp) - vx * SNI(xp);
            } else {
                w.x = g0.x + g1.x; w.y = g0.y + g1.y;
            }
#pragma unroll
            for (int mm = 0; mm < 8; mm++) {
                const int ke = KOF(2*mm);
                A[mm].x += w.x * CSI(ke*xp) + w.y * SNI(ke*xp);
                A[mm].y += w.y * CSI(ke*xp) - w.x * SNI(ke*xp);
            }
        }
        __syncthreads();               // all P reads done; reuse P as OUT
        float2* OUTS = P;              // OUT[(kx*16+ky)*4 + s]
#pragma unroll
        for (int mm = 0; mm < 8; mm++) {
            int m = 2 * mm + par;      // m == kx
            OUTS[(m * 16 + ky) * 4 + s] = A[mm];
        }
    }
    __syncthreads();

    // flush: per (kx,ky) write 4 consecutive kk (= sp*4..sp*4+3) as 2 float4
#pragma unroll
    for (int j = 0; j < 2; j++) {
        int u = tid + j * 128;        // u = kx*16+ky
        float2 v0 = P[u * 4 + 0];
        float2 v1 = P[u * 4 + 1];
        float2 v2 = P[u * 4 + 2];
        float2 v3 = P[u * 4 + 3];
        float4* dst = (float4*)&g_fd[(size_t)bc * NMODE + (size_t)u * 96 + sp * 4];
        dst[0] = make_float4(v0.x, v0.y, v1.x, v1.y);
        dst[1] = make_float4(v2.x, v2.y, v3.x, v3.y);
    }
}

// ---------------- spectral channel mix, 192 thr, 10 outputs/thread ----------
// grid (128, 2): blockIdx.y selects 10 output channels; g_fd read 2x not 4x
__global__ void __launch_bounds__(192) k_mult(const float2* __restrict__ swl) {
    __shared__ float2 SE[20][192];      // [o_local*2 + b][tid]  (30 KB)
    int tid = threadIdx.x;
    int m = blockIdx.x * 192 + tid;     // grid.x = 128
    int ob = blockIdx.y * 10;
    int kt = m % 6; int r = m / 6;
    int kz = r & 15, ky = (r >> 4) & 15, kx = (r >> 8) & 15;
    int oct = ((kx >> 3) << 2) | ((ky >> 3) << 1) | (kz >> 3);
    int lm = (((kx & 7) * 8 + (ky & 7)) * 8 + (kz & 7)) * 6 + kt;
    const float2* wbase = swl + (size_t)oct * 1228800 + lm + (size_t)ob * 3072;

    float2 a0[10], a1[10];
#pragma unroll
    for (int o = 0; o < 10; o++) { a0[o] = make_float2(0.f,0.f); a1[o] = make_float2(0.f,0.f); }

    for (int i = 0; i < NCH; i++) {
        float2 x0 = __ldg(&g_fd[(size_t)i * NMODE + m]);
        float2 x1 = __ldg(&g_fd[(size_t)(NCH + i) * NMODE + m]);
        const float2* wp = wbase + (size_t)i * 61440;
#pragma unroll
        for (int o = 0; o < 10; o++) {
            float2 w = __ldg(&wp[o * 3072]);
            a0[o].x += w.x * x0.x - w.y * x0.y;
            a0[o].y += w.x * x0.y + w.y * x0.x;
            a1[o].x += w.x * x1.x - w.y * x1.y;
            a1[o].y += w.x * x1.y + w.y * x1.x;
        }
    }
#pragma unroll
    for (int o = 0; o < 10; o++) {
        SE[o * 2 + 0][tid] = a0[o];
        SE[o * 2 + 1][tid] = a1[o];
    }
    __syncthreads();

    // flush: tid -> (g, kt2, kz2), kz fastest in global address
    {
        int g = tid / 96, rr = tid % 96;
        int kt2 = rr / 16, kz2 = rr % 16;
        int kxky = blockIdx.x * 2 + g;
        int kx2 = kxky >> 4, ky2 = kxky & 15;
        size_t dstoff = (size_t)(kx2 * 6 + kt2) * 256 + ky2 * 16 + kz2;
        int srci = g * 96 + kz2 * 6 + kt2;
#pragma unroll
        for (int row = 0; row < 20; row++) {
            int oo = row >> 1, bb = row & 1;
            g_fe[(size_t)(bb * NCH + ob + oo) * NMODE + dstoff] = SE[row][srci];
        }
    }
}

// ---------------- inv Y + Z, radix-2 imm, contiguous g_fe reads -------------
__global__ void __launch_bounds__(128) k_invZY() {
    __shared__ float2 G[4 * 256];        // [s][ky*16+kz]
    __shared__ float2 H1[4 * 32 * 17];   // [s][y][kz] pad 17
    __shared__ float2 OUT[4 * 32 * 33];  // [s][y][z] pad 33
    int bid = blockIdx.x;
    int sp = bid % 24, bo = bid / 24;
    int b = bo / NCH, o = bo % NCH;
    int tid = threadIdx.x;

    {
        const float4* srcv = (const float4*)(g_fe + (size_t)bo * NMODE + (size_t)sp * 1024);
        float4* dstv = (float4*)G;
#pragma unroll
        for (int q = 0; q < 4; q++) dstv[q * 128 + tid] = srcv[q * 128 + tid];
    }
    __syncthreads();

    // stage invY: 64 threads = (s 4, kz 16); Se/So for y pairs
    if (tid < 64) {
        int s = tid >> 4, kz = tid & 15;
        float2 Se[16], So[16];
#pragma unroll
        for (int y = 0; y < 16; y++) { Se[y] = make_float2(0.f,0.f); So[y] = make_float2(0.f,0.f); }
#pragma unroll
        for (int m = 0; m < 16; m++) {
            const int k = KOF(m);
            float2 g = G[s * 256 + m * 16 + kz];
#pragma unroll
            for (int y = 0; y < 16; y++) {
                const float c = CSI(k*y) * (1.0f/32.0f);
                const float sn = SNI(k*y) * (1.0f/32.0f);
                float2& acc = (m & 1) ? So[y] : Se[y];
                acc.x += g.x * c - g.y * sn;
                acc.y += g.y * c + g.x * sn;
            }
        }
#pragma unroll
        for (int y = 0; y < 16; y++) {
            H1[s * 544 + y * 17 + kz]        = make_float2(Se[y].x + So[y].x, Se[y].y + So[y].y);
            H1[s * 544 + (y + 16) * 17 + kz] = make_float2(Se[y].x - So[y].x, Se[y].y - So[y].y);
        }
    }
    __syncthreads();

    // stage invZ: 128 threads = (s 4, y 32); Se/So for z pairs
    {
        int s = tid >> 5, y = tid & 31;
        float2 Se[16], So[16];
#pragma unroll
        for (int z = 0; z < 16; z++) { Se[z] = make_float2(0.f,0.f); So[z] = make_float2(0.f,0.f); }
#pragma unroll
        for (int m = 0; m < 16; m++) {
            const int k = KOF(m);
            float2 g = H1[s * 544 + y * 17 + m];
#pragma unroll
            for (int z = 0; z < 16; z++) {
                const float c = CSI(k*z) * (1.0f/32.0f);
                const float sn = SNI(k*z) * (1.0f/32.0f);
                float2& acc = (m & 1) ? So[z] : Se[z];
                acc.x += g.x * c - g.y * sn;
                acc.y += g.y * c + g.x * sn;
            }
        }
#pragma unroll
        for (int z = 0; z < 16; z++) {
            OUT[s * 1056 + y * 33 + z]      = make_float2(Se[z].x + So[z].x, Se[z].y + So[z].y);
            OUT[s * 1056 + y * 33 + z + 16] = make_float2(Se[z].x - So[z].x, Se[z].y - So[z].y);
        }
    }
    __syncthreads();

#pragma unroll
    for (int q = 0; q < 8; q++) {
        int yz = q * 128 + tid;
        int y = yz >> 5, z = yz & 31;
        float2 v0 = OUT[0 * 1056 + y * 33 + z];
        float2 v1 = OUT[1 * 1056 + y * 33 + z];
        float2 v2 = OUT[2 * 1056 + y * 33 + z];
        float2 v3 = OUT[3 * 1056 + y * 33 + z];
        float4* dst = (float4*)&g_fb[((size_t)b * 1024 + yz) * 1920 + o * 96 + sp * 4];
        dst[0] = make_float4(v0.x, v0.y, v1.x, v1.y);
        dst[1] = make_float4(v2.x, v2.y, v3.x, v3.y);
    }
}

// ---------------- fused: invX (radix-2 imm) + invT + pointwise + GELU -------
__global__ void __launch_bounds__(256) k_fused(const float* __restrict__ ww,
                                               const float* __restrict__ wb,
                                               int src, int do_gelu) {
    __shared__ __align__(16) float2 Gs[1920];   // [o][kx*6+kt]
    __shared__ float2 E[3840];    // [o][x*6+kt]
    __shared__ float  sww[400];
    __shared__ float  swb[NCH];

    const float* hin  = src ? g_hB : g_hA;
    float*       hout = src ? g_hA : g_hB;

    int b = blockIdx.x >> 10;
    int yz = blockIdx.x & 1023;
    int tid = threadIdx.x;

    // hoist h loads to the very top — overlap DRAM latency with stage 1
    int t = tid & 15, x0 = tid >> 4, x1 = x0 + 16;
    size_t p0 = (size_t)x0 * 16384 + (size_t)yz * 16 + t;
    size_t p1 = (size_t)x1 * 16384 + (size_t)yz * 16 + t;
    float hv0[NCH], hv1[NCH];
#pragma unroll
    for (int i = 0; i < NCH; i++) {
        hv0[i] = hin[(size_t)(b * NCH + i) * NSP + p0];
        hv1[i] = hin[(size_t)(b * NCH + i) * NSP + p1];
    }

    // coalesced contiguous fill: 960 float4
    {
        const float4* srcv = (const float4*)&g_fb[((size_t)b * 1024 + yz) * 1920];
        float4* dstv = (float4*)Gs;
        for (int q = tid; q < 960; q += 256) dstv[q] = srcv[q];
    }
    for (int q = tid; q < 400; q += 256) sww[q] = ww[q];
    if (tid < NCH) swb[tid] = wb[tid];
    __syncthreads();

    // stage invX: 120 threads = (o 20, kt 6); Se/So for x pairs
    if (tid < 120) {
        int o = tid / 6, kt = tid % 6;
        float2 Se[16], So[16];
#pragma unroll
        for (int x = 0; x < 16; x++) { Se[x] = make_float2(0.f,0.f); So[x] = make_float2(0.f,0.f); }
#pragma unroll
        for (int m = 0; m < 16; m++) {
            const int k = KOF(m);
            float2 g = Gs[o * 96 + m * 6 + kt];
#pragma unroll
            for (int x = 0; x < 16; x++) {
                const float c = CSI(k*x) * (1.0f/32.0f);
                const float sn = SNI(k*x) * (1.0f/32.0f);
                float2& acc = (m & 1) ? So[x] : Se[x];
                acc.x += g.x * c - g.y * sn;
                acc.y += g.y * c + g.x * sn;
            }
        }
#pragma unroll
        for (int x = 0; x < 16; x++) {
            E[o * 192 + x * 6 + kt]        = make_float2(Se[x].x + So[x].x, Se[x].y + So[x].y);
            E[o * 192 + (x + 16) * 6 + kt] = make_float2(Se[x].x - So[x].x, Se[x].y - So[x].y);
        }
    }
    __syncthreads();

    // stage 2: 2 points per thread, processed together in the o-loop
    {
        float2 wt[6];
#pragma unroll
        for (int k = 0; k < 6; k++) wt[k] = d_invT[t * 6 + k];

#pragma unroll 4
        for (int o = 0; o < NCH; o++) {
            float acc0 = swb[o], acc1 = acc0;
#pragma unroll
            for (int i = 0; i < NCH; i++) {
                float w = sww[o * NCH + i];
                acc0 += w * hv0[i];
                acc1 += w * hv1[i];
            }
            const float2* eo0 = &E[o * 192 + x0 * 6];
            const float2* eo1 = &E[o * 192 + x1 * 6];
            float s0 = 0.f, s1 = 0.f;
#pragma unroll
            for (int k = 0; k < 6; k++) {
                s0 += eo0[k].x * wt[k].x - eo0[k].y * wt[k].y;
                s1 += eo1[k].x * wt[k].x - eo1[k].y * wt[k].y;
            }
            float v0 = acc0 + s0, v1 = acc1 + s1;
            if (do_gelu) { v0 = gelu_exact(v0); v1 = gelu_exact(v1); }
            hout[(size_t)(b * NCH + o) * NSP + p0] = v0;
            hout[(size_t)(b * NCH + o) * NSP + p1] = v1;
        }
    }
}

// ---------------- head: fc1(20->128)+GELU+fc2(128->1), 2 pts/thread ---------
__global__ void __launch_bounds__(256) k_head(const float* __restrict__ fc1w,
                                              const float* __restrict__ fc1b,
                                              const float* __restrict__ fc2w,
                                              const float* __restrict__ fc2b,
                                              float* __restrict__ out) {
    __shared__ float w1[NCH * 128];
    __shared__ float b1[128], w2[128];

    int b = blockIdx.x >> 10;
    int pbase = (blockIdx.x & 1023) * 512;
    int tid = threadIdx.x;
    int p0 = pbase + tid, p1 = p0 + 256;

    float hv0[NCH], hv1[NCH];
#pragma unroll
    for (int i = 0; i < NCH; i++) {
        hv0[i] = g_hA[(size_t)(b * NCH + i) * NSP + p0];
        hv1[i] = g_hA[(size_t)(b * NCH + i) * NSP + p1];
    }
    for (int q = tid; q < NCH * 128; q += 256) w1[q] = fc1w[q];
    if (tid < 128) { b1[tid] = fc1b[tid]; w2[tid] = fc2w[tid]; }
    __syncthreads();

    float acc0 = __ldg(&fc2b[0]), acc1 = acc0;
#pragma unroll 4
    for (int j = 0; j < 128; j++) {
        float a0 = b1[j], a1 = b1[j];
#pragma unroll
        for (int i = 0; i < NCH; i++) {
            float w = w1[i * 128 + j];
            a0 += hv0[i] * w;
            a1 += hv1[i] * w;
        }
        a0 = gelu_exact(a0); a1 = gelu_exact(a1);
        float w2j = w2[j];
        acc0 += a0 * w2j; acc1 += a1 * w2j;
    }
    out[(size_t)b * NSP + p0] = acc0;
    out[(size_t)b * NSP + p1] = acc1;
}

// ---------------- launch ----------------------------------------------------
extern "C" void kernel_launch(void* const* d_in, const int* in_sizes, int n_in,
                              void* d_out, int out_size) {
    const float* x     = (const float*)d_in[0];
    const float* fc0_w = (const float*)d_in[1];
    const float* fc0_b = (const float*)d_in[2];
    const float* sw    = (const float*)d_in[3];
    const float* ww    = (const float*)d_in[4];
    const float* wb    = (const float*)d_in[5];
    const float* fc1_w = (const float*)d_in[6];
    const float* fc1_b = (const float*)d_in[7];
    const float* fc2_w = (const float*)d_in[8];
    const float* fc2_b = (const float*)d_in[9];
    float* out = (float*)d_out;

    k_init<<<1, 128>>>();
    k_lift<<<4096, 256>>>(x, fc0_w, fc0_b);

    int src = 0;
    for (int l = 0; l < 4; l++) {
        k_fwdTZ<<<NB*NCH*64, 128>>>(src);
        k_fwdYX<<<NB*NCH*24, 128>>>();
        const float2* swl = (const float2*)sw + (size_t)l * 9830400;
        dim3 mg(128, 2);
        k_mult<<<mg, 192>>>(swl);
        k_invZY<<<NB*NCH*24, 128>>>();
        k_fused<<<NB*1024, 256>>>(ww + l * 400, wb + l * NCH, src, (l < 3) ? 1 : 0);
        src ^= 1;
    }
    k_head<<<2048, 256>>>(fc1_w, fc1_b, fc2_w, fc2_b, out);
}

// round 14
// speedup vs baseline: 1.1307x; 1.1307x over previous
#include <cuda_runtime.h>
#include <math.h>

// ---------------- static scratch ----------------
#define NSP 524288            // 32*32*32*16 points per (b,c)
#define NCH 20
#define NB  2
#define NMODE 24576           // 16*16*16*6 kept modes

__device__ float  g_hA[NB*NCH*NSP];          // 84 MB
__device__ float  g_hB[NB*NCH*NSP];          // 84 MB
__device__ float2 g_fa[NB*NCH*96*1024];      // S1 [bc][kz*6+kt][x*32+y]
__device__ float2 g_fb[NB*1024*1920];        // S2 [b][y*32+z][o*96 + kx*6+kt]  (yz-major)
__device__ float2 g_fd[NB*NCH*NMODE];        // x_ft  (m = (kx*16+ky)*96 + kz*6+kt)
__device__ float2 g_fe[NB*NCH*NMODE];        // out_ft SLAB-MAJOR: [(kx*6+kt)*256 + ky*16+kz]

// cos(pi*j/16); sin(pi*j/16) = CSX[(j+24)&31]
__device__ static const float CSX[32] = {
     1.000000000f,  0.980785280f,  0.923879533f,  0.831469612f,
     0.707106781f,  0.555570233f,  0.382683432f,  0.195090322f,
     0.000000000f, -0.195090322f, -0.382683432f, -0.555570233f,
    -0.707106781f, -0.831469612f, -0.923879533f, -0.980785280f,
    -1.000000000f, -0.980785280f, -0.923879533f, -0.831469612f,
    -0.707106781f, -0.555570233f, -0.382683432f, -0.195090322f,
     0.000000000f,  0.195090322f,  0.382683432f,  0.555570233f,
     0.707106781f,  0.831469612f,  0.923879533f,  0.980785280f };

#define CSI(p) CSX[(p) & 31]
#define SNI(p) CSX[((p) + 24) & 31]
#define KOF(m) ((m) + ((m) >= 8 ? 16 : 0))

__device__ float2 d_invT[96];   // [t(16)][k(6)] ((k==0?1:2)/16)*(cos,sin)(+2pi k t/16)

__device__ __forceinline__ float gelu_exact(float v) {
    return 0.5f * v * (1.0f + erff(v * 0.70710678118654752f));
}

__global__ void k_init() {
    int tid = threadIdx.x;
    if (tid < 96) {
        int t2 = tid / 6, k2 = tid % 6;
        int ph2 = (k2 * t2) & 15;
        float wk = (k2 == 0 ? 1.0f : 2.0f) * (1.0f/16.0f);
        float s2, c2; sincospif((float)ph2 / 8.0f, &s2, &c2);
        d_invT[tid] = make_float2(wk * c2, wk * s2);
    }
}

// ---------------- lift ------------------------------------------------------
__global__ void __launch_bounds__(256) k_lift(const float* __restrict__ x,
                                              const float* __restrict__ w,
                                              const float* __restrict__ bias) {
    int tid = blockIdx.x * blockDim.x + threadIdx.x;
    if (tid >= NB * NSP) return;
    int b = tid / NSP, p = tid % NSP;
    float xi[5];
#pragma unroll
    for (int i = 0; i < 5; i++) xi[i] = x[(size_t)tid * 5 + i];
#pragma unroll
    for (int c = 0; c < NCH; c++) {
        float a = __ldg(&bias[c]);
#pragma unroll
        for (int i = 0; i < 5; i++) a += xi[i] * __ldg(&w[i * NCH + c]);
        g_hA[(size_t)(b * NCH + c) * NSP + p] = a;
    }
}

// ---------------- fwd T (16->6) + Z (32->16), radix-2 imm -------------------
__global__ void __launch_bounds__(128) k_fwdTZ(int src) {
    __shared__ float2 st[6 * 16 * 33];            // [kt][yl][z] pad 33
    const float* h = src ? g_hB : g_hA;
    int bid = blockIdx.x;
    int yh = bid & 1, x = (bid >> 1) & 31, bc = bid >> 6;
    int tid = threadIdx.x;

#pragma unroll
    for (int q = 0; q < 4; q++) {
        int p = q * 128 + tid;
        int yl = p >> 5, z = p & 31;
        const float4* src4 = (const float4*)(h + (size_t)bc * NSP + x * 16384
                                             + (yh * 16 + yl) * 512 + z * 16);
        float v[16];
#pragma unroll
        for (int r = 0; r < 4; r++) {
            float4 f = src4[r];
            v[r*4+0]=f.x; v[r*4+1]=f.y; v[r*4+2]=f.z; v[r*4+3]=f.w;
        }
        float ue[8], uo[8];
#pragma unroll
        for (int t = 0; t < 8; t++) { ue[t] = v[t] + v[t+8]; uo[t] = v[t] - v[t+8]; }
#pragma unroll
        for (int k = 0; k < 6; k++) {
            const float* wsrc = (k & 1) ? uo : ue;
            float ax = 0.f, ay = 0.f;
#pragma unroll
            for (int t = 0; t < 8; t++) {
                ax += wsrc[t] * CSI(2*k*t);
                ay -= wsrc[t] * SNI(2*k*t);
            }
            st[(k * 16 + yl) * 33 + z] = make_float2(ax, ay);
        }
    }
    __syncthreads();

    // stage Z: 96 threads = (kt 6, yl 16); radix-2, 16 accs
    if (tid < 96) {
        int kt = tid >> 4, yl = tid & 15;
        float2 A[16];
#pragma unroll
        for (int m = 0; m < 16; m++) A[m] = make_float2(0.f, 0.f);
#pragma unroll
        for (int zp = 0; zp < 16; zp++) {
            float2 g0 = st[(kt * 16 + yl) * 33 + zp];
            float2 g1 = st[(kt * 16 + yl) * 33 + zp + 16];
            float2 u = make_float2(g0.x + g1.x, g0.y + g1.y);
            float2 v = make_float2(g0.x - g1.x, g0.y - g1.y);
#pragma unroll
            for (int mm = 0; mm < 8; mm++) {
                const int ke = KOF(2*mm);
                A[2*mm].x   += u.x * CSI(ke*zp) + u.y * SNI(ke*zp);
                A[2*mm].y   += u.y * CSI(ke*zp) - u.x * SNI(ke*zp);
                const int ko = KOF(2*mm+1);
                A[2*mm+1].x += v.x * CSI(ko*zp) + v.y * SNI(ko*zp);
                A[2*mm+1].y += v.y * CSI(ko*zp) - v.x * SNI(ko*zp);
            }
        }
#pragma unroll
        for (int m = 0; m < 16; m++)
            g_fa[((size_t)bc * 96 + m * 6 + kt) * 1024 + x * 32 + yh * 16 + yl] = A[m];
    }
}

// ---------------- fwd Y + X, radix-2 imm, 4 slabs / 128 threads -------------
__global__ void __launch_bounds__(128) k_fwdYX() {
    __shared__ float2 P[4 * 32 * 33];   // [s][x][y] pad 33; reused as OUT[1024]
    int bid = blockIdx.x;
    int sp = bid % 24, bc = bid / 24;
    int tid = threadIdx.x;
    const float2* s1 = g_fa + ((size_t)bc * 96 + sp * 4) * 1024;
#pragma unroll
    for (int q = 0; q < 32; q++) {
        int u = q * 128 + tid;
        int s = u >> 10, r = u & 1023;
        P[s * 1056 + (r >> 5) * 33 + (r & 31)] = s1[u];
    }
    __syncthreads();

    // stage Y: (s 4, x 32) = 128; radix-2 over y, 16 ky accs; in-place write
    {
        int s = tid >> 5, x = tid & 31;
        float2 A[16];
#pragma unroll
        for (int m = 0; m < 16; m++) A[m] = make_float2(0.f, 0.f);
#pragma unroll
        for (int yp = 0; yp < 16; yp++) {
            float2 g0 = P[s * 1056 + x * 33 + yp];
            float2 g1 = P[s * 1056 + x * 33 + yp + 16];
            float2 u = make_float2(g0.x + g1.x, g0.y + g1.y);
            float2 v = make_float2(g0.x - g1.x, g0.y - g1.y);
#pragma unroll
            for (int mm = 0; mm < 8; mm++) {
                const int ke = KOF(2*mm);
                A[2*mm].x   += u.x * CSI(ke*yp) + u.y * SNI(ke*yp);
                A[2*mm].y   += u.y * CSI(ke*yp) - u.x * SNI(ke*yp);
                const int ko = KOF(2*mm+1);
                A[2*mm+1].x += v.x * CSI(ko*yp) + v.y * SNI(ko*yp);
                A[2*mm+1].y += v.y * CSI(ko*yp) - v.x * SNI(ko*yp);
            }
        }
#pragma unroll
        for (int m = 0; m < 16; m++) P[s * 1056 + x * 33 + m] = A[m];
    }
    __syncthreads();

    // stage X: (s 4, ky 16, par 2) = 128; mode-parity split with twiddle fold
    {
        int s = tid >> 5;
        int r = tid & 31; int ky = r >> 1; int par = r & 1;
        float2 A[8];
#pragma unroll
        for (int mm = 0; mm < 8; mm++) A[mm] = make_float2(0.f, 0.f);
#pragma unroll
        for (int xp = 0; xp < 16; xp++) {
            float2 g0 = P[s * 1056 + xp * 33 + ky];
            float2 g1 = P[s * 1056 + (xp + 16) * 33 + ky];
            float2 w;
            if (par) {
                float vx = g0.x - g1.x, vy = g0.y - g1.y;
                w.x = vx * CSI(xp) + vy * SNI(xp);
                w.y = vy * CSI(xp) - vx * SNI(xp);
            } else {
                w.x = g0.x + g1.x; w.y = g0.y + g1.y;
            }
#pragma unroll
            for (int mm = 0; mm < 8; mm++) {
                const int ke = KOF(2*mm);
                A[mm].x += w.x * CSI(ke*xp) + w.y * SNI(ke*xp);
                A[mm].y += w.y * CSI(ke*xp) - w.x * SNI(ke*xp);
            }
        }
        __syncthreads();               // all P reads done; reuse P as OUT
        float2* OUTS = P;              // OUT[(kx*16+ky)*4 + s]
#pragma unroll
        for (int mm = 0; mm < 8; mm++) {
            int m = 2 * mm + par;      // m == kx
            OUTS[(m * 16 + ky) * 4 + s] = A[mm];
        }
    }
    __syncthreads();

    // flush: per (kx,ky) write 4 consecutive kk (= sp*4..sp*4+3) as 2 float4
#pragma unroll
    for (int j = 0; j < 2; j++) {
        int u = tid + j * 128;        // u = kx*16+ky
        float2 v0 = P[u * 4 + 0];
        float2 v1 = P[u * 4 + 1];
        float2 v2 = P[u * 4 + 2];
        float2 v3 = P[u * 4 + 3];
        float4* dst = (float4*)&g_fd[(size_t)bc * NMODE + (size_t)u * 96 + sp * 4];
        dst[0] = make_float4(v0.x, v0.y, v1.x, v1.y);
        dst[1] = make_float4(v2.x, v2.y, v3.x, v3.y);
    }
}

// ---------------- spectral channel mix, 192 thr, staged coalesced flush -----
// g_fe output layout: [(b*NCH+o)][ (kx*6+kt)*256 + ky*16+kz ]
__global__ void __launch_bounds__(192) k_mult(const float2* __restrict__ swl) {
    __shared__ float2 SE[10][192];      // [o_local*2 + b][tid]
    int tid = threadIdx.x;
    int m = blockIdx.x * 192 + tid;     // grid.x = 128
    int ob = blockIdx.y * 5;
    int kt = m % 6; int r = m / 6;
    int kz = r & 15, ky = (r >> 4) & 15, kx = (r >> 8) & 15;
    int oct = ((kx >> 3) << 2) | ((ky >> 3) << 1) | (kz >> 3);
    int lm = (((kx & 7) * 8 + (ky & 7)) * 8 + (kz & 7)) * 6 + kt;
    const float2* wbase = swl + (size_t)oct * 1228800 + lm + (size_t)ob * 3072;

    float2 a0[5], a1[5];
#pragma unroll
    for (int o = 0; o < 5; o++) { a0[o] = make_float2(0.f,0.f); a1[o] = make_float2(0.f,0.f); }

#pragma unroll 2
    for (int i = 0; i < NCH; i++) {
        float2 x0 = __ldg(&g_fd[(size_t)i * NMODE + m]);
        float2 x1 = __ldg(&g_fd[(size_t)(NCH + i) * NMODE + m]);
        const float2* wp = wbase + (size_t)i * 61440;
#pragma unroll
        for (int o = 0; o < 5; o++) {
            float2 w = __ldg(&wp[o * 3072]);
            a0[o].x += w.x * x0.x - w.y * x0.y;
            a0[o].y += w.x * x0.y + w.y * x0.x;
            a1[o].x += w.x * x1.x - w.y * x1.y;
            a1[o].y += w.x * x1.y + w.y * x1.x;
        }
    }
#pragma unroll
    for (int o = 0; o < 5; o++) {
        SE[o * 2 + 0][tid] = a0[o];
        SE[o * 2 + 1][tid] = a1[o];
    }
    __syncthreads();

    {
        int g = tid / 96, rr = tid % 96;
        int kt2 = rr / 16, kz2 = rr % 16;
        int kxky = blockIdx.x * 2 + g;
        int kx2 = kxky >> 4, ky2 = kxky & 15;
        size_t dstoff = (size_t)(kx2 * 6 + kt2) * 256 + ky2 * 16 + kz2;
        int srci = g * 96 + kz2 * 6 + kt2;
#pragma unroll
        for (int row = 0; row < 10; row++) {
            int oo = row >> 1, bb = row & 1;
            g_fe[(size_t)(bb * NCH + ob + oo) * NMODE + dstoff] = SE[row][srci];
        }
    }
}

// ---------------- inv Y + Z, radix-2 imm, contiguous g_fe reads -------------
__global__ void __launch_bounds__(128) k_invZY() {
    __shared__ float2 G[4 * 256];        // [s][ky*16+kz]
    __shared__ float2 H1[4 * 32 * 17];   // [s][y][kz] pad 17
    __shared__ float2 OUT[4 * 32 * 33];  // [s][y][z] pad 33
    int bid = blockIdx.x;
    int sp = bid % 24, bo = bid / 24;
    int b = bo / NCH, o = bo % NCH;
    int tid = threadIdx.x;

    {
        const float4* srcv = (const float4*)(g_fe + (size_t)bo * NMODE + (size_t)sp * 1024);
        float4* dstv = (float4*)G;
#pragma unroll
        for (int q = 0; q < 4; q++) dstv[q * 128 + tid] = srcv[q * 128 + tid];
    }
    __syncthreads();

    // stage invY: 64 threads = (s 4, kz 16); Se/So for y pairs
    if (tid < 64) {
        int s = tid >> 4, kz = tid & 15;
        float2 Se[16], So[16];
#pragma unroll
        for (int y = 0; y < 16; y++) { Se[y] = make_float2(0.f,0.f); So[y] = make_float2(0.f,0.f); }
#pragma unroll
        for (int m = 0; m < 16; m++) {
            const int k = KOF(m);
            float2 g = G[s * 256 + m * 16 + kz];
#pragma unroll
            for (int y = 0; y < 16; y++) {
                const float c = CSI(k*y) * (1.0f/32.0f);
                const float sn = SNI(k*y) * (1.0f/32.0f);
                float2& acc = (m & 1) ? So[y] : Se[y];
                acc.x += g.x * c - g.y * sn;
                acc.y += g.y * c + g.x * sn;
            }
        }
#pragma unroll
        for (int y = 0; y < 16; y++) {
            H1[s * 544 + y * 17 + kz]        = make_float2(Se[y].x + So[y].x, Se[y].y + So[y].y);
            H1[s * 544 + (y + 16) * 17 + kz] = make_float2(Se[y].x - So[y].x, Se[y].y - So[y].y);
        }
    }
    __syncthreads();

    // stage invZ: 128 threads = (s 4, y 32); Se/So for z pairs
    {
        int s = tid >> 5, y = tid & 31;
        float2 Se[16], So[16];
#pragma unroll
        for (int z = 0; z < 16; z++) { Se[z] = make_float2(0.f,0.f); So[z] = make_float2(0.f,0.f); }
#pragma unroll
        for (int m = 0; m < 16; m++) {
            const int k = KOF(m);
            float2 g = H1[s * 544 + y * 17 + m];
#pragma unroll
            for (int z = 0; z < 16; z++) {
                const float c = CSI(k*z) * (1.0f/32.0f);
                const float sn = SNI(k*z) * (1.0f/32.0f);
                float2& acc = (m & 1) ? So[z] : Se[z];
                acc.x += g.x * c - g.y * sn;
                acc.y += g.y * c + g.x * sn;
            }
        }
#pragma unroll
        for (int z = 0; z < 16; z++) {
            OUT[s * 1056 + y * 33 + z]      = make_float2(Se[z].x + So[z].x, Se[z].y + So[z].y);
            OUT[s * 1056 + y * 33 + z + 16] = make_float2(Se[z].x - So[z].x, Se[z].y - So[z].y);
        }
    }
    __syncthreads();

#pragma unroll
    for (int q = 0; q < 8; q++) {
        int yz = q * 128 + tid;
        int y = yz >> 5, z = yz & 31;
        float2 v0 = OUT[0 * 1056 + y * 33 + z];
        float2 v1 = OUT[1 * 1056 + y * 33 + z];
        float2 v2 = OUT[2 * 1056 + y * 33 + z];
        float2 v3 = OUT[3 * 1056 + y * 33 + z];
        float4* dst = (float4*)&g_fb[((size_t)b * 1024 + yz) * 1920 + o * 96 + sp * 4];
        dst[0] = make_float4(v0.x, v0.y, v1.x, v1.y);
        dst[1] = make_float4(v2.x, v2.y, v3.x, v3.y);
    }
}

// ---------------- fused: invX (radix-2 imm) + invT + pointwise + GELU -------
__global__ void __launch_bounds__(256) k_fused(const float* __restrict__ ww,
                                               const float* __restrict__ wb,
                                               int src, int do_gelu) {
    __shared__ __align__(16) float2 Gs[1920];   // [o][kx*6+kt]
    __shared__ float2 E[3840];    // [o][x*6+kt]
    __shared__ float  sww[400];
    __shared__ float  swb[NCH];

    const float* hin  = src ? g_hB : g_hA;
    float*       hout = src ? g_hA : g_hB;

    int b = blockIdx.x >> 10;
    int yz = blockIdx.x & 1023;
    int tid = threadIdx.x;

    // hoist h loads to the very top — overlap DRAM latency with stage 1
    int t = tid & 15, x0 = tid >> 4, x1 = x0 + 16;
    size_t p0 = (size_t)x0 * 16384 + (size_t)yz * 16 + t;
    size_t p1 = (size_t)x1 * 16384 + (size_t)yz * 16 + t;
    float hv0[NCH], hv1[NCH];
#pragma unroll
    for (int i = 0; i < NCH; i++) {
        hv0[i] = hin[(size_t)(b * NCH + i) * NSP + p0];
        hv1[i] = hin[(size_t)(b * NCH + i) * NSP + p1];
    }

    // coalesced contiguous fill: 960 float4
    {
        const float4* srcv = (const float4*)&g_fb[((size_t)b * 1024 + yz) * 1920];
        float4* dstv = (float4*)Gs;
        for (int q = tid; q < 960; q += 256) dstv[q] = srcv[q];
    }
    for (int q = tid; q < 400; q += 256) sww[q] = ww[q];
    if (tid < NCH) swb[tid] = wb[tid];
    __syncthreads();

    // stage invX: 120 threads = (o 20, kt 6); Se/So for x pairs
    if (tid < 120) {
        int o = tid / 6, kt = tid % 6;
        float2 Se[16], So[16];
#pragma unroll
        for (int x = 0; x < 16; x++) { Se[x] = make_float2(0.f,0.f); So[x] = make_float2(0.f,0.f); }
#pragma unroll
        for (int m = 0; m < 16; m++) {
            const int k = KOF(m);
            float2 g = Gs[o * 96 + m * 6 + kt];
#pragma unroll
            for (int x = 0; x < 16; x++) {
                const float c = CSI(k*x) * (1.0f/32.0f);
                const float sn = SNI(k*x) * (1.0f/32.0f);
                float2& acc = (m & 1) ? So[x] : Se[x];
                acc.x += g.x * c - g.y * sn;
                acc.y += g.y * c + g.x * sn;
            }
        }
#pragma unroll
        for (int x = 0; x < 16; x++) {
            E[o * 192 + x * 6 + kt]        = make_float2(Se[x].x + So[x].x, Se[x].y + So[x].y);
            E[o * 192 + (x + 16) * 6 + kt] = make_float2(Se[x].x - So[x].x, Se[x].y - So[x].y);
        }
    }
    __syncthreads();

    // stage 2: 2 points per thread, processed together in the o-loop
    {
        float2 wt[6];
#pragma unroll
        for (int k = 0; k < 6; k++) wt[k] = d_invT[t * 6 + k];

#pragma unroll 4
        for (int o = 0; o < NCH; o++) {
            float acc0 = swb[o], acc1 = acc0;
#pragma unroll
            for (int i = 0; i < NCH; i++) {
                float w = sww[o * NCH + i];
                acc0 += w * hv0[i];
                acc1 += w * hv1[i];
            }
            const float2* eo0 = &E[o * 192 + x0 * 6];
            const float2* eo1 = &E[o * 192 + x1 * 6];
            float s0 = 0.f, s1 = 0.f;
#pragma unroll
            for (int k = 0; k < 6; k++) {
                s0 += eo0[k].x * wt[k].x - eo0[k].y * wt[k].y;
                s1 += eo1[k].x * wt[k].x - eo1[k].y * wt[k].y;
            }
            float v0 = acc0 + s0, v1 = acc1 + s1;
            if (do_gelu) { v0 = gelu_exact(v0); v1 = gelu_exact(v1); }
            hout[(size_t)(b * NCH + o) * NSP + p0] = v0;
            hout[(size_t)(b * NCH + o) * NSP + p1] = v1;
        }
    }
}

// ---------------- head: fc1(20->128)+GELU+fc2(128->1), 2 pts/thread ---------
__global__ void __launch_bounds__(256) k_head(const float* __restrict__ fc1w,
                                              const float* __restrict__ fc1b,
                                              const float* __restrict__ fc2w,
                                              const float* __restrict__ fc2b,
                                              float* __restrict__ out) {
    __shared__ float w1[NCH * 128];
    __shared__ float b1[128], w2[128];

    int b = blockIdx.x >> 10;
    int pbase = (blockIdx.x & 1023) * 512;
    int tid = threadIdx.x;
    int p0 = pbase + tid, p1 = p0 + 256;

    float hv0[NCH], hv1[NCH];
#pragma unroll
    for (int i = 0; i < NCH; i++) {
        hv0[i] = g_hA[(size_t)(b * NCH + i) * NSP + p0];
        hv1[i] = g_hA[(size_t)(b * NCH + i) * NSP + p1];
    }
    for (int q = tid; q < NCH * 128; q += 256) w1[q] = fc1w[q];
    if (tid < 128) { b1[tid] = fc1b[tid]; w2[tid] = fc2w[tid]; }
    __syncthreads();

    float acc0 = __ldg(&fc2b[0]), acc1 = acc0;
#pragma unroll 4
    for (int j = 0; j < 128; j++) {
        float a0 = b1[j], a1 = b1[j];
#pragma unroll
        for (int i = 0; i < NCH; i++) {
            float w = w1[i * 128 + j];
            a0 += hv0[i] * w;
            a1 += hv1[i] * w;
        }
        a0 = gelu_exact(a0); a1 = gelu_exact(a1);
        float w2j = w2[j];
        acc0 += a0 * w2j; acc1 += a1 * w2j;
    }
    out[(size_t)b * NSP + p0] = acc0;
    out[(size_t)b * NSP + p1] = acc1;
}

// ---------------- launch ----------------------------------------------------
extern "C" void kernel_launch(void* const* d_in, const int* in_sizes, int n_in,
                              void* d_out, int out_size) {
    const float* x     = (const float*)d_in[0];
    const float* fc0_w = (const float*)d_in[1];
    const float* fc0_b = (const float*)d_in[2];
    const float* sw    = (const float*)d_in[3];
    const float* ww    = (const float*)d_in[4];
    const float* wb    = (const float*)d_in[5];
    const float* fc1_w = (const float*)d_in[6];
    const float* fc1_b = (const float*)d_in[7];
    const float* fc2_w = (const float*)d_in[8];
    const float* fc2_b = (const float*)d_in[9];
    float* out = (float*)d_out;

    k_init<<<1, 128>>>();
    k_lift<<<4096, 256>>>(x, fc0_w, fc0_b);

    int src = 0;
    for (int l = 0; l < 4; l++) {
        k_fwdTZ<<<NB*NCH*64, 128>>>(src);
        k_fwdYX<<<NB*NCH*24, 128>>>();
        const float2* swl = (const float2*)sw + (size_t)l * 9830400;
        dim3 mg(128, 4);
        k_mult<<<mg, 192>>>(swl);
        k_invZY<<<NB*NCH*24, 128>>>();
        k_fused<<<NB*1024, 256>>>(ww + l * 400, wb + l * NCH, src, (l < 3) ? 1 : 0);
        src ^= 1;
    }
    k_head<<<2048, 256>>>(fc1_w, fc1_b, fc2_w, fc2_b, out);
}

// round 15
// speedup vs baseline: 1.1366x; 1.0052x over previous
#include <cuda_runtime.h>
#include <math.h>

// ---------------- static scratch ----------------
#define NSP 524288            // 32*32*32*16 points per (b,c)
#define NCH 20
#define NB  2
#define NMODE 24576           // 16*16*16*6 kept modes

__device__ float  g_hA[NB*NCH*NSP];          // 84 MB
__device__ float  g_hB[NB*NCH*NSP];          // 84 MB
__device__ float2 g_fa[NB*NCH*96*1024];      // S1 [bc][kz*6+kt][x*32+y]
__device__ float2 g_fb[NB*1024*1920];        // S2 [b][y*32+z][o*96 + kx*6+kt]  (yz-major)
__device__ float2 g_fd[NB*NCH*NMODE];        // x_ft  (m = (kx*16+ky)*96 + kz*6+kt)
__device__ float2 g_fe[NB*NCH*NMODE];        // out_ft SLAB-MAJOR: [(kx*6+kt)*256 + ky*16+kz]

// cos(pi*j/16); sin(pi*j/16) = CSX[(j+24)&31]
__device__ static const float CSX[32] = {
     1.000000000f,  0.980785280f,  0.923879533f,  0.831469612f,
     0.707106781f,  0.555570233f,  0.382683432f,  0.195090322f,
     0.000000000f, -0.195090322f, -0.382683432f, -0.555570233f,
    -0.707106781f, -0.831469612f, -0.923879533f, -0.980785280f,
    -1.000000000f, -0.980785280f, -0.923879533f, -0.831469612f,
    -0.707106781f, -0.555570233f, -0.382683432f, -0.195090322f,
     0.000000000f,  0.195090322f,  0.382683432f,  0.555570233f,
     0.707106781f,  0.831469612f,  0.923879533f,  0.980785280f };

#define CSI(p) CSX[(p) & 31]
#define SNI(p) CSX[((p) + 24) & 31]
#define KOF(m) ((m) + ((m) >= 8 ? 16 : 0))

__device__ float2 d_invT[96];   // [t(16)][k(6)] ((k==0?1:2)/16)*(cos,sin)(+2pi k t/16)

__device__ __forceinline__ float gelu_exact(float v) {
    return 0.5f * v * (1.0f + erff(v * 0.70710678118654752f));
}

__global__ void k_init() {
    int tid = threadIdx.x;
    if (tid < 96) {
        int t2 = tid / 6, k2 = tid % 6;
        int ph2 = (k2 * t2) & 15;
        float wk = (k2 == 0 ? 1.0f : 2.0f) * (1.0f/16.0f);
        float s2, c2; sincospif((float)ph2 / 8.0f, &s2, &c2);
        d_invT[tid] = make_float2(wk * c2, wk * s2);
    }
}

// ---------------- lift: 4 points/thread, float4 stores ----------------------
__global__ void __launch_bounds__(256) k_lift(const float* __restrict__ x,
                                              const float* __restrict__ w,
                                              const float* __restrict__ bias) {
    int tid = blockIdx.x * blockDim.x + threadIdx.x;   // NB*NSP/4 threads
    if (tid >= NB * NSP / 4) return;
    int b = tid / (NSP / 4), r = tid % (NSP / 4);
    size_t p4 = (size_t)r * 4;

    float xi[4][5];
    const float* xs = x + ((size_t)b * NSP + p4) * 5;
#pragma unroll
    for (int q = 0; q < 4; q++)
#pragma unroll
        for (int i = 0; i < 5; i++) xi[q][i] = xs[q * 5 + i];

#pragma unroll
    for (int c = 0; c < NCH; c++) {
        float bc = __ldg(&bias[c]);
        float4 a;
        float* av = (float*)&a;
#pragma unroll
        for (int q = 0; q < 4; q++) {
            float s = bc;
#pragma unroll
            for (int i = 0; i < 5; i++) s += xi[q][i] * __ldg(&w[i * NCH + c]);
            av[q] = s;
        }
        *(float4*)&g_hA[(size_t)(b * NCH + c) * NSP + p4] = a;
    }
}

// ---------------- fwd T (16->6) + Z (32->16), radix-2 imm -------------------
__global__ void __launch_bounds__(128) k_fwdTZ(int src) {
    __shared__ float2 st[6 * 16 * 33];            // [kt][yl][z] pad 33
    const float* h = src ? g_hB : g_hA;
    int bid = blockIdx.x;
    int yh = bid & 1, x = (bid >> 1) & 31, bc = bid >> 6;
    int tid = threadIdx.x;

#pragma unroll
    for (int q = 0; q < 4; q++) {
        int p = q * 128 + tid;
        int yl = p >> 5, z = p & 31;
        const float4* src4 = (const float4*)(h + (size_t)bc * NSP + x * 16384
                                             + (yh * 16 + yl) * 512 + z * 16);
        float v[16];
#pragma unroll
        for (int r = 0; r < 4; r++) {
            float4 f = src4[r];
            v[r*4+0]=f.x; v[r*4+1]=f.y; v[r*4+2]=f.z; v[r*4+3]=f.w;
        }
        float ue[8], uo[8];
#pragma unroll
        for (int t = 0; t < 8; t++) { ue[t] = v[t] + v[t+8]; uo[t] = v[t] - v[t+8]; }
#pragma unroll
        for (int k = 0; k < 6; k++) {
            const float* wsrc = (k & 1) ? uo : ue;
            float ax = 0.f, ay = 0.f;
#pragma unroll
            for (int t = 0; t < 8; t++) {
                ax += wsrc[t] * CSI(2*k*t);
                ay -= wsrc[t] * SNI(2*k*t);
            }
            st[(k * 16 + yl) * 33 + z] = make_float2(ax, ay);
        }
    }
    __syncthreads();

    // stage Z: 96 threads = (kt 6, yl 16); radix-2, 16 accs
    if (tid < 96) {
        int kt = tid >> 4, yl = tid & 15;
        float2 A[16];
#pragma unroll
        for (int m = 0; m < 16; m++) A[m] = make_float2(0.f, 0.f);
#pragma unroll
        for (int zp = 0; zp < 16; zp++) {
            float2 g0 = st[(kt * 16 + yl) * 33 + zp];
            float2 g1 = st[(kt * 16 + yl) * 33 + zp + 16];
            float2 u = make_float2(g0.x + g1.x, g0.y + g1.y);
            float2 v = make_float2(g0.x - g1.x, g0.y - g1.y);
#pragma unroll
            for (int mm = 0; mm < 8; mm++) {
                const int ke = KOF(2*mm);
                A[2*mm].x   += u.x * CSI(ke*zp) + u.y * SNI(ke*zp);
                A[2*mm].y   += u.y * CSI(ke*zp) - u.x * SNI(ke*zp);
                const int ko = KOF(2*mm+1);
                A[2*mm+1].x += v.x * CSI(ko*zp) + v.y * SNI(ko*zp);
                A[2*mm+1].y += v.y * CSI(ko*zp) - v.x * SNI(ko*zp);
            }
        }
#pragma unroll
        for (int m = 0; m < 16; m++)
            g_fa[((size_t)bc * 96 + m * 6 + kt) * 1024 + x * 32 + yh * 16 + yl] = A[m];
    }
}

// ---------------- fwd Y + X, radix-2 imm, 4 slabs / 128 threads -------------
__global__ void __launch_bounds__(128) k_fwdYX() {
    __shared__ float2 P[4 * 32 * 33];   // [s][x][y] pad 33; reused as OUT[1024]
    int bid = blockIdx.x;
    int sp = bid % 24, bc = bid / 24;
    int tid = threadIdx.x;
    const float2* s1 = g_fa + ((size_t)bc * 96 + sp * 4) * 1024;
#pragma unroll
    for (int q = 0; q < 32; q++) {
        int u = q * 128 + tid;
        int s = u >> 10, r = u & 1023;
        P[s * 1056 + (r >> 5) * 33 + (r & 31)] = s1[u];
    }
    __syncthreads();

    // stage Y: (s 4, x 32) = 128; radix-2 over y, 16 ky accs; in-place write
    {
        int s = tid >> 5, x = tid & 31;
        float2 A[16];
#pragma unroll
        for (int m = 0; m < 16; m++) A[m] = make_float2(0.f, 0.f);
#pragma unroll
        for (int yp = 0; yp < 16; yp++) {
            float2 g0 = P[s * 1056 + x * 33 + yp];
            float2 g1 = P[s * 1056 + x * 33 + yp + 16];
            float2 u = make_float2(g0.x + g1.x, g0.y + g1.y);
            float2 v = make_float2(g0.x - g1.x, g0.y - g1.y);
#pragma unroll
            for (int mm = 0; mm < 8; mm++) {
                const int ke = KOF(2*mm);
                A[2*mm].x   += u.x * CSI(ke*yp) + u.y * SNI(ke*yp);
                A[2*mm].y   += u.y * CSI(ke*yp) - u.x * SNI(ke*yp);
                const int ko = KOF(2*mm+1);
                A[2*mm+1].x += v.x * CSI(ko*yp) + v.y * SNI(ko*yp);
                A[2*mm+1].y += v.y * CSI(ko*yp) - v.x * SNI(ko*yp);
            }
        }
#pragma unroll
        for (int m = 0; m < 16; m++) P[s * 1056 + x * 33 + m] = A[m];
    }
    __syncthreads();

    // stage X: (s 4, ky 16, par 2) = 128; mode-parity split with twiddle fold
    {
        int s = tid >> 5;
        int r = tid & 31; int ky = r >> 1; int par = r & 1;
        float2 A[8];
#pragma unroll
        for (int mm = 0; mm < 8; mm++) A[mm] = make_float2(0.f, 0.f);
#pragma unroll
        for (int xp = 0; xp < 16; xp++) {
            float2 g0 = P[s * 1056 + xp * 33 + ky];
            float2 g1 = P[s * 1056 + (xp + 16) * 33 + ky];
            float2 w;
            if (par) {
                float vx = g0.x - g1.x, vy = g0.y - g1.y;
                w.x = vx * CSI(xp) + vy * SNI(xp);
                w.y = vy * CSI(xp) - vx * SNI(xp);
            } else {
                w.x = g0.x + g1.x; w.y = g0.y + g1.y;
            }
#pragma unroll
            for (int mm = 0; mm < 8; mm++) {
                const int ke = KOF(2*mm);
                A[mm].x += w.x * CSI(ke*xp) + w.y * SNI(ke*xp);
                A[mm].y += w.y * CSI(ke*xp) - w.x * SNI(ke*xp);
            }
        }
        __syncthreads();               // all P reads done; reuse P as OUT
        float2* OUTS = P;              // OUT[(kx*16+ky)*4 + s]
#pragma unroll
        for (int mm = 0; mm < 8; mm++) {
            int m = 2 * mm + par;      // m == kx
            OUTS[(m * 16 + ky) * 4 + s] = A[mm];
        }
    }
    __syncthreads();

    // flush: per (kx,ky) write 4 consecutive kk (= sp*4..sp*4+3) as 2 float4
#pragma unroll
    for (int j = 0; j < 2; j++) {
        int u = tid + j * 128;        // u = kx*16+ky
        float2 v0 = P[u * 4 + 0];
        float2 v1 = P[u * 4 + 1];
        float2 v2 = P[u * 4 + 2];
        float2 v3 = P[u * 4 + 3];
        float4* dst = (float4*)&g_fd[(size_t)bc * NMODE + (size_t)u * 96 + sp * 4];
        dst[0] = make_float4(v0.x, v0.y, v1.x, v1.y);
        dst[1] = make_float4(v2.x, v2.y, v3.x, v3.y);
    }
}

// ---------------- spectral channel mix, 192 thr, staged coalesced flush -----
__global__ void __launch_bounds__(192) k_mult(const float2* __restrict__ swl) {
    __shared__ float2 SE[10][192];      // [o_local*2 + b][tid]
    int tid = threadIdx.x;
    int m = blockIdx.x * 192 + tid;     // grid.x = 128
    int ob = blockIdx.y * 5;
    int kt = m % 6; int r = m / 6;
    int kz = r & 15, ky = (r >> 4) & 15, kx = (r >> 8) & 15;
    int oct = ((kx >> 3) << 2) | ((ky >> 3) << 1) | (kz >> 3);
    int lm = (((kx & 7) * 8 + (ky & 7)) * 8 + (kz & 7)) * 6 + kt;
    const float2* wbase = swl + (size_t)oct * 1228800 + lm + (size_t)ob * 3072;

    float2 a0[5], a1[5];
#pragma unroll
    for (int o = 0; o < 5; o++) { a0[o] = make_float2(0.f,0.f); a1[o] = make_float2(0.f,0.f); }

#pragma unroll 4
    for (int i = 0; i < NCH; i++) {
        float2 x0 = __ldg(&g_fd[(size_t)i * NMODE + m]);
        float2 x1 = __ldg(&g_fd[(size_t)(NCH + i) * NMODE + m]);
        const float2* wp = wbase + (size_t)i * 61440;
#pragma unroll
        for (int o = 0; o < 5; o++) {
            float2 w = __ldg(&wp[o * 3072]);
            a0[o].x += w.x * x0.x - w.y * x0.y;
            a0[o].y += w.x * x0.y + w.y * x0.x;
            a1[o].x += w.x * x1.x - w.y * x1.y;
            a1[o].y += w.x * x1.y + w.y * x1.x;
        }
    }
#pragma unroll
    for (int o = 0; o < 5; o++) {
        SE[o * 2 + 0][tid] = a0[o];
        SE[o * 2 + 1][tid] = a1[o];
    }
    __syncthreads();

    {
        int g = tid / 96, rr = tid % 96;
        int kt2 = rr / 16, kz2 = rr % 16;
        int kxky = blockIdx.x * 2 + g;
        int kx2 = kxky >> 4, ky2 = kxky & 15;
        size_t dstoff = (size_t)(kx2 * 6 + kt2) * 256 + ky2 * 16 + kz2;
        int srci = g * 96 + kz2 * 6 + kt2;
#pragma unroll
        for (int row = 0; row < 10; row++) {
            int oo = row >> 1, bb = row & 1;
            g_fe[(size_t)(bb * NCH + ob + oo) * NMODE + dstoff] = SE[row][srci];
        }
    }
}

// ---------------- inv Y + Z, radix-2 imm, contiguous g_fe reads -------------
__global__ void __launch_bounds__(128) k_invZY() {
    __shared__ float2 G[4 * 256];        // [s][ky*16+kz]
    __shared__ float2 H1[4 * 32 * 17];   // [s][y][kz] pad 17
    __shared__ float2 OUT[4 * 32 * 33];  // [s][y][z] pad 33
    int bid = blockIdx.x;
    int sp = bid % 24, bo = bid / 24;
    int b = bo / NCH, o = bo % NCH;
    int tid = threadIdx.x;

    {
        const float4* srcv = (const float4*)(g_fe + (size_t)bo * NMODE + (size_t)sp * 1024);
        float4* dstv = (float4*)G;
#pragma unroll
        for (int q = 0; q < 4; q++) dstv[q * 128 + tid] = srcv[q * 128 + tid];
    }
    __syncthreads();

    // stage invY: 64 threads = (s 4, kz 16); Se/So for y pairs
    if (tid < 64) {
        int s = tid >> 4, kz = tid & 15;
        float2 Se[16], So[16];
#pragma unroll
        for (int y = 0; y < 16; y++) { Se[y] = make_float2(0.f,0.f); So[y] = make_float2(0.f,0.f); }
#pragma unroll
        for (int m = 0; m < 16; m++) {
            const int k = KOF(m);
            float2 g = G[s * 256 + m * 16 + kz];
#pragma unroll
            for (int y = 0; y < 16; y++) {
                const float c = CSI(k*y) * (1.0f/32.0f);
                const float sn = SNI(k*y) * (1.0f/32.0f);
                float2& acc = (m & 1) ? So[y] : Se[y];
                acc.x += g.x * c - g.y * sn;
                acc.y += g.y * c + g.x * sn;
            }
        }
#pragma unroll
        for (int y = 0; y < 16; y++) {
            H1[s * 544 + y * 17 + kz]        = make_float2(Se[y].x + So[y].x, Se[y].y + So[y].y);
            H1[s * 544 + (y + 16) * 17 + kz] = make_float2(Se[y].x - So[y].x, Se[y].y - So[y].y);
        }
    }
    __syncthreads();

    // stage invZ: 128 threads = (s 4, y 32); Se/So for z pairs
    {
        int s = tid >> 5, y = tid & 31;
        float2 Se[16], So[16];
#pragma unroll
        for (int z = 0; z < 16; z++) { Se[z] = make_float2(0.f,0.f); So[z] = make_float2(0.f,0.f); }
#pragma unroll
        for (int m = 0; m < 16; m++) {
            const int k = KOF(m);
            float2 g = H1[s * 544 + y * 17 + m];
#pragma unroll
            for (int z = 0; z < 16; z++) {
                const float c = CSI(k*z) * (1.0f/32.0f);
                const float sn = SNI(k*z) * (1.0f/32.0f);
                float2& acc = (m & 1) ? So[z] : Se[z];
                acc.x += g.x * c - g.y * sn;
                acc.y += g.y * c + g.x * sn;
            }
        }
#pragma unroll
        for (int z = 0; z < 16; z++) {
            OUT[s * 1056 + y * 33 + z]      = make_float2(Se[z].x + So[z].x, Se[z].y + So[z].y);
            OUT[s * 1056 + y * 33 + z + 16] = make_float2(Se[z].x - So[z].x, Se[z].y - So[z].y);
        }
    }
    __syncthreads();

#pragma unroll
    for (int q = 0; q < 8; q++) {
        int yz = q * 128 + tid;
        int y = yz >> 5, z = yz & 31;
        float2 v0 = OUT[0 * 1056 + y * 33 + z];
        float2 v1 = OUT[1 * 1056 + y * 33 + z];
        float2 v2 = OUT[2 * 1056 + y * 33 + z];
        float2 v3 = OUT[3 * 1056 + y * 33 + z];
        float4* dst = (float4*)&g_fb[((size_t)b * 1024 + yz) * 1920 + o * 96 + sp * 4];
        dst[0] = make_float4(v0.x, v0.y, v1.x, v1.y);
        dst[1] = make_float4(v2.x, v2.y, v3.x, v3.y);
    }
}

// ---------------- fused: invX (radix-2 imm) + invT + pointwise + GELU -------
__global__ void __launch_bounds__(256) k_fused(const float* __restrict__ ww,
                                               const float* __restrict__ wb,
                                               int src, int do_gelu) {
    __shared__ __align__(16) float2 Gs[1920];   // [o][kx*6+kt]
    __shared__ float2 E[3840];    // [o][x*6+kt]
    __shared__ float  sww[400];
    __shared__ float  swb[NCH];

    const float* hin  = src ? g_hB : g_hA;
    float*       hout = src ? g_hA : g_hB;

    int b = blockIdx.x >> 10;
    int yz = blockIdx.x & 1023;
    int tid = threadIdx.x;

    // hoist h loads to the very top — overlap DRAM latency with stage 1
    int t = tid & 15, x0 = tid >> 4, x1 = x0 + 16;
    size_t p0 = (size_t)x0 * 16384 + (size_t)yz * 16 + t;
    size_t p1 = (size_t)x1 * 16384 + (size_t)yz * 16 + t;
    float hv0[NCH], hv1[NCH];
#pragma unroll
    for (int i = 0; i < NCH; i++) {
        hv0[i] = hin[(size_t)(b * NCH + i) * NSP + p0];
        hv1[i] = hin[(size_t)(b * NCH + i) * NSP + p1];
    }

    // coalesced contiguous fill: 960 float4
    {
        const float4* srcv = (const float4*)&g_fb[((size_t)b * 1024 + yz) * 1920];
        float4* dstv = (float4*)Gs;
        for (int q = tid; q < 960; q += 256) dstv[q] = srcv[q];
    }
    for (int q = tid; q < 400; q += 256) sww[q] = ww[q];
    if (tid < NCH) swb[tid] = wb[tid];
    __syncthreads();

    // stage invX: 120 threads = (o 20, kt 6); Se/So for x pairs
    if (tid < 120) {
        int o = tid / 6, kt = tid % 6;
        float2 Se[16], So[16];
#pragma unroll
        for (int x = 0; x < 16; x++) { Se[x] = make_float2(0.f,0.f); So[x] = make_float2(0.f,0.f); }
#pragma unroll
        for (int m = 0; m < 16; m++) {
            const int k = KOF(m);
            float2 g = Gs[o * 96 + m * 6 + kt];
#pragma unroll
            for (int x = 0; x < 16; x++) {
                const float c = CSI(k*x) * (1.0f/32.0f);
                const float sn = SNI(k*x) * (1.0f/32.0f);
                float2& acc = (m & 1) ? So[x] : Se[x];
                acc.x += g.x * c - g.y * sn;
                acc.y += g.y * c + g.x * sn;
            }
        }
#pragma unroll
        for (int x = 0; x < 16; x++) {
            E[o * 192 + x * 6 + kt]        = make_float2(Se[x].x + So[x].x, Se[x].y + So[x].y);
            E[o * 192 + (x + 16) * 6 + kt] = make_float2(Se[x].x - So[x].x, Se[x].y - So[x].y);
        }
    }
    __syncthreads();

    // stage 2: 2 points per thread, processed together in the o-loop
    {
        float2 wt[6];
#pragma unroll
        for (int k = 0; k < 6; k++) wt[k] = d_invT[t * 6 + k];

#pragma unroll 4
        for (int o = 0; o < NCH; o++) {
            float acc0 = swb[o], acc1 = acc0;
#pragma unroll
            for (int i = 0; i < NCH; i++) {
                float w = sww[o * NCH + i];
                acc0 += w * hv0[i];
                acc1 += w * hv1[i];
            }
            const float2* eo0 = &E[o * 192 + x0 * 6];
            const float2* eo1 = &E[o * 192 + x1 * 6];
            float s0 = 0.f, s1 = 0.f;
#pragma unroll
            for (int k = 0; k < 6; k++) {
                s0 += eo0[k].x * wt[k].x - eo0[k].y * wt[k].y;
                s1 += eo1[k].x * wt[k].x - eo1[k].y * wt[k].y;
            }
            float v0 = acc0 + s0, v1 = acc1 + s1;
            if (do_gelu) { v0 = gelu_exact(v0); v1 = gelu_exact(v1); }
            hout[(size_t)(b * NCH + o) * NSP + p0] = v0;
            hout[(size_t)(b * NCH + o) * NSP + p1] = v1;
        }
    }
}

// ---------------- head: fc1(20->128)+GELU+fc2(128->1), 2 pts/thread ---------
__global__ void __launch_bounds__(256) k_head(const float* __restrict__ fc1w,
                                              const float* __restrict__ fc1b,
                                              const float* __restrict__ fc2w,
                                              const float* __restrict__ fc2b,
                                              float* __restrict__ out) {
    __shared__ float w1[NCH * 128];
    __shared__ float b1[128], w2[128];

    int b = blockIdx.x >> 10;
    int pbase = (blockIdx.x & 1023) * 512;
    int tid = threadIdx.x;
    int p0 = pbase + tid, p1 = p0 + 256;

    float hv0[NCH], hv1[NCH];
#pragma unroll
    for (int i = 0; i < NCH; i++) {
        hv0[i] = g_hA[(size_t)(b * NCH + i) * NSP + p0];
        hv1[i] = g_hA[(size_t)(b * NCH + i) * NSP + p1];
    }
    for (int q = tid; q < NCH * 128; q += 256) w1[q] = fc1w[q];
    if (tid < 128) { b1[tid] = fc1b[tid]; w2[tid] = fc2w[tid]; }
    __syncthreads();

    float acc0 = __ldg(&fc2b[0]), acc1 = acc0;
#pragma unroll 4
    for (int j = 0; j < 128; j++) {
        float a0 = b1[j], a1 = b1[j];
#pragma unroll
        for (int i = 0; i < NCH; i++) {
            float w = w1[i * 128 + j];
            a0 += hv0[i] * w;
            a1 += hv1[i] * w;
        }
        a0 = gelu_exact(a0); a1 = gelu_exact(a1);
        float w2j = w2[j];
        acc0 += a0 * w2j; acc1 += a1 * w2j;
    }
    out[(size_t)b * NSP + p0] = acc0;
    out[(size_t)b * NSP + p1] = acc1;
}

// ---------------- launch ----------------------------------------------------
extern "C" void kernel_launch(void* const* d_in, const int* in_sizes, int n_in,
                              void* d_out, int out_size) {
    const float* x     = (const float*)d_in[0];
    const float* fc0_w = (const float*)d_in[1];
    const float* fc0_b = (const float*)d_in[2];
    const float* sw    = (const float*)d_in[3];
    const float* ww    = (const float*)d_in[4];
    const float* wb    = (const float*)d_in[5];
    const float* fc1_w = (const float*)d_in[6];
    const float* fc1_b = (const float*)d_in[7];
    const float* fc2_w = (const float*)d_in[8];
    const float* fc2_b = (const float*)d_in[9];
    float* out = (float*)d_out;

    k_init<<<1, 128>>>();
    k_lift<<<1024, 256>>>(x, fc0_w, fc0_b);

    int src = 0;
    for (int l = 0; l < 4; l++) {
        k_fwdTZ<<<NB*NCH*64, 128>>>(src);
        k_fwdYX<<<NB*NCH*24, 128>>>();
        const float2* swl = (const float2*)sw + (size_t)l * 9830400;
        dim3 mg(128, 4);
        k_mult<<<mg, 192>>>(swl);
        k_invZY<<<NB*NCH*24, 128>>>();
        k_fused<<<NB*1024, 256>>>(ww + l * 400, wb + l * NCH, src, (l < 3) ? 1 : 0);
        src ^= 1;
    }
    k_head<<<2048, 256>>>(fc1_w, fc1_b, fc2_w, fc2_b, out);
}

// round 16
// speedup vs baseline: 1.1389x; 1.0020x over previous
#include <cuda_runtime.h>
#include <math.h>

// ---------------- static scratch ----------------
#define NSP 524288            // 32*32*32*16 points per (b,c)
#define NCH 20
#define NB  2
#define NMODE 24576           // 16*16*16*6 kept modes

__device__ float  g_hA[NB*NCH*NSP];          // 84 MB
__device__ float  g_hB[NB*NCH*NSP];          // 84 MB
__device__ float2 g_fa[NB*NCH*96*1024];      // S1 [bc][kz*6+kt][x*32+y]
__device__ float2 g_fb[NB*1024*1920];        // S2 [b][y*32+z][o*96 + kx*6+kt]  (yz-major)
__device__ float2 g_fd[NB*NCH*NMODE];        // x_ft  (m = (kx*16+ky)*96 + kz*6+kt)
__device__ float2 g_fe[NB*NCH*NMODE];        // out_ft SLAB-MAJOR: [(kx*6+kt)*256 + ky*16+kz]

// cos(pi*j/16); sin(pi*j/16) = CSX[(j+24)&31]
__device__ static const float CSX[32] = {
     1.000000000f,  0.980785280f,  0.923879533f,  0.831469612f,
     0.707106781f,  0.555570233f,  0.382683432f,  0.195090322f,
     0.000000000f, -0.195090322f, -0.382683432f, -0.555570233f,
    -0.707106781f, -0.831469612f, -0.923879533f, -0.980785280f,
    -1.000000000f, -0.980785280f, -0.923879533f, -0.831469612f,
    -0.707106781f, -0.555570233f, -0.382683432f, -0.195090322f,
     0.000000000f,  0.195090322f,  0.382683432f,  0.555570233f,
     0.707106781f,  0.831469612f,  0.923879533f,  0.980785280f };

#define CSI(p) CSX[(p) & 31]
#define SNI(p) CSX[((p) + 24) & 31]
#define KOF(m) ((m) + ((m) >= 8 ? 16 : 0))

__device__ float2 d_invT[96];   // [t(16)][k(6)] ((k==0?1:2)/16)*(cos,sin)(+2pi k t/16)

__device__ __forceinline__ float gelu_exact(float v) {
    return 0.5f * v * (1.0f + erff(v * 0.70710678118654752f));
}

__global__ void k_init() {
    int tid = threadIdx.x;
    if (tid < 96) {
        int t2 = tid / 6, k2 = tid % 6;
        int ph2 = (k2 * t2) & 15;
        float wk = (k2 == 0 ? 1.0f : 2.0f) * (1.0f/16.0f);
        float s2, c2; sincospif((float)ph2 / 8.0f, &s2, &c2);
        d_invT[tid] = make_float2(wk * c2, wk * s2);
    }
}

// ---------------- lift: 4 points/thread, float4 stores ----------------------
__global__ void __launch_bounds__(256) k_lift(const float* __restrict__ x,
                                              const float* __restrict__ w,
                                              const float* __restrict__ bias) {
    int tid = blockIdx.x * blockDim.x + threadIdx.x;   // NB*NSP/4 threads
    if (tid >= NB * NSP / 4) return;
    int b = tid / (NSP / 4), r = tid % (NSP / 4);
    size_t p4 = (size_t)r * 4;

    float xi[4][5];
    const float* xs = x + ((size_t)b * NSP + p4) * 5;
#pragma unroll
    for (int q = 0; q < 4; q++)
#pragma unroll
        for (int i = 0; i < 5; i++) xi[q][i] = xs[q * 5 + i];

#pragma unroll
    for (int c = 0; c < NCH; c++) {
        float bc = __ldg(&bias[c]);
        float4 a;
        float* av = (float*)&a;
#pragma unroll
        for (int q = 0; q < 4; q++) {
            float s = bc;
#pragma unroll
            for (int i = 0; i < 5; i++) s += xi[q][i] * __ldg(&w[i * NCH + c]);
            av[q] = s;
        }
        *(float4*)&g_hA[(size_t)(b * NCH + c) * NSP + p4] = a;
    }
}

// ---------------- fwd T (16->6) + Z (32->16), radix-2 imm -------------------
__global__ void __launch_bounds__(128) k_fwdTZ(int src) {
    __shared__ float2 st[6 * 16 * 33];            // [kt][yl][z] pad 33
    const float* h = src ? g_hB : g_hA;
    int bid = blockIdx.x;
    int yh = bid & 1, x = (bid >> 1) & 31, bc = bid >> 6;
    int tid = threadIdx.x;

#pragma unroll
    for (int q = 0; q < 4; q++) {
        int p = q * 128 + tid;
        int yl = p >> 5, z = p & 31;
        const float4* src4 = (const float4*)(h + (size_t)bc * NSP + x * 16384
                                             + (yh * 16 + yl) * 512 + z * 16);
        float v[16];
#pragma unroll
        for (int r = 0; r < 4; r++) {
            float4 f = src4[r];
            v[r*4+0]=f.x; v[r*4+1]=f.y; v[r*4+2]=f.z; v[r*4+3]=f.w;
        }
        float ue[8], uo[8];
#pragma unroll
        for (int t = 0; t < 8; t++) { ue[t] = v[t] + v[t+8]; uo[t] = v[t] - v[t+8]; }
#pragma unroll
        for (int k = 0; k < 6; k++) {
            const float* wsrc = (k & 1) ? uo : ue;
            float ax = 0.f, ay = 0.f;
#pragma unroll
            for (int t = 0; t < 8; t++) {
                ax += wsrc[t] * CSI(2*k*t);
                ay -= wsrc[t] * SNI(2*k*t);
            }
            st[(k * 16 + yl) * 33 + z] = make_float2(ax, ay);
        }
    }
    __syncthreads();

    // stage Z: 96 threads = (kt 6, yl 16); radix-2, 16 accs
    if (tid < 96) {
        int kt = tid >> 4, yl = tid & 15;
        float2 A[16];
#pragma unroll
        for (int m = 0; m < 16; m++) A[m] = make_float2(0.f, 0.f);
#pragma unroll
        for (int zp = 0; zp < 16; zp++) {
            float2 g0 = st[(kt * 16 + yl) * 33 + zp];
            float2 g1 = st[(kt * 16 + yl) * 33 + zp + 16];
            float2 u = make_float2(g0.x + g1.x, g0.y + g1.y);
            float2 v = make_float2(g0.x - g1.x, g0.y - g1.y);
#pragma unroll
            for (int mm = 0; mm < 8; mm++) {
                const int ke = KOF(2*mm);
                A[2*mm].x   += u.x * CSI(ke*zp) + u.y * SNI(ke*zp);
                A[2*mm].y   += u.y * CSI(ke*zp) - u.x * SNI(ke*zp);
                const int ko = KOF(2*mm+1);
                A[2*mm+1].x += v.x * CSI(ko*zp) + v.y * SNI(ko*zp);
                A[2*mm+1].y += v.y * CSI(ko*zp) - v.x * SNI(ko*zp);
            }
        }
#pragma unroll
        for (int m = 0; m < 16; m++)
            g_fa[((size_t)bc * 96 + m * 6 + kt) * 1024 + x * 32 + yh * 16 + yl] = A[m];
    }
}

// ---------------- fwd Y + X, radix-2 imm, 4 slabs / 128 threads -------------
__global__ void __launch_bounds__(128) k_fwdYX() {
    __shared__ float2 P[4 * 32 * 33];   // [s][x][y] pad 33; reused as OUT[1024]
    int bid = blockIdx.x;
    int sp = bid % 24, bc = bid / 24;
    int tid = threadIdx.x;
    const float2* s1 = g_fa + ((size_t)bc * 96 + sp * 4) * 1024;
#pragma unroll
    for (int q = 0; q < 32; q++) {
        int u = q * 128 + tid;
        int s = u >> 10, r = u & 1023;
        P[s * 1056 + (r >> 5) * 33 + (r & 31)] = s1[u];
    }
    __syncthreads();

    // stage Y: (s 4, x 32) = 128; radix-2 over y, 16 ky accs; in-place write
    {
        int s = tid >> 5, x = tid & 31;
        float2 A[16];
#pragma unroll
        for (int m = 0; m < 16; m++) A[m] = make_float2(0.f, 0.f);
#pragma unroll
        for (int yp = 0; yp < 16; yp++) {
            float2 g0 = P[s * 1056 + x * 33 + yp];
            float2 g1 = P[s * 1056 + x * 33 + yp + 16];
            float2 u = make_float2(g0.x + g1.x, g0.y + g1.y);
            float2 v = make_float2(g0.x - g1.x, g0.y - g1.y);
#pragma unroll
            for (int mm = 0; mm < 8; mm++) {
                const int ke = KOF(2*mm);
                A[2*mm].x   += u.x * CSI(ke*yp) + u.y * SNI(ke*yp);
                A[2*mm].y   += u.y * CSI(ke*yp) - u.x * SNI(ke*yp);
                const int ko = KOF(2*mm+1);
                A[2*mm+1].x += v.x * CSI(ko*yp) + v.y * SNI(ko*yp);
                A[2*mm+1].y += v.y * CSI(ko*yp) - v.x * SNI(ko*yp);
            }
        }
#pragma unroll
        for (int m = 0; m < 16; m++) P[s * 1056 + x * 33 + m] = A[m];
    }
    __syncthreads();

    // stage X: (s 4, ky 16, par 2) = 128; mode-parity split with twiddle fold
    {
        int s = tid >> 5;
        int r = tid & 31; int ky = r >> 1; int par = r & 1;
        float2 A[8];
#pragma unroll
        for (int mm = 0; mm < 8; mm++) A[mm] = make_float2(0.f, 0.f);
#pragma unroll
        for (int xp = 0; xp < 16; xp++) {
            float2 g0 = P[s * 1056 + xp * 33 + ky];
            float2 g1 = P[s * 1056 + (xp + 16) * 33 + ky];
            float2 w;
            if (par) {
                float vx = g0.x - g1.x, vy = g0.y - g1.y;
                w.x = vx * CSI(xp) + vy * SNI(xp);
                w.y = vy * CSI(xp) - vx * SNI(xp);
            } else {
                w.x = g0.x + g1.x; w.y = g0.y + g1.y;
            }
#pragma unroll
            for (int mm = 0; mm < 8; mm++) {
                const int ke = KOF(2*mm);
                A[mm].x += w.x * CSI(ke*xp) + w.y * SNI(ke*xp);
                A[mm].y += w.y * CSI(ke*xp) - w.x * SNI(ke*xp);
            }
        }
        __syncthreads();               // all P reads done; reuse P as OUT
        float2* OUTS = P;              // OUT[(kx*16+ky)*4 + s]
#pragma unroll
        for (int mm = 0; mm < 8; mm++) {
            int m = 2 * mm + par;      // m == kx
            OUTS[(m * 16 + ky) * 4 + s] = A[mm];
        }
    }
    __syncthreads();

    // flush: per (kx,ky) write 4 consecutive kk (= sp*4..sp*4+3) as 2 float4
#pragma unroll
    for (int j = 0; j < 2; j++) {
        int u = tid + j * 128;        // u = kx*16+ky
        float2 v0 = P[u * 4 + 0];
        float2 v1 = P[u * 4 + 1];
        float2 v2 = P[u * 4 + 2];
        float2 v3 = P[u * 4 + 3];
        float4* dst = (float4*)&g_fd[(size_t)bc * NMODE + (size_t)u * 96 + sp * 4];
        dst[0] = make_float4(v0.x, v0.y, v1.x, v1.y);
        dst[1] = make_float4(v2.x, v2.y, v3.x, v3.y);
    }
}

// ---------------- spectral channel mix, 192 thr, staged coalesced flush -----
__global__ void __launch_bounds__(192) k_mult(const float2* __restrict__ swl) {
    __shared__ float2 SE[10][192];      // [o_local*2 + b][tid]
    int tid = threadIdx.x;
    int m = blockIdx.x * 192 + tid;     // grid.x = 128
    int ob = blockIdx.y * 5;
    int kt = m % 6; int r = m / 6;
    int kz = r & 15, ky = (r >> 4) & 15, kx = (r >> 8) & 15;
    int oct = ((kx >> 3) << 2) | ((ky >> 3) << 1) | (kz >> 3);
    int lm = (((kx & 7) * 8 + (ky & 7)) * 8 + (kz & 7)) * 6 + kt;
    const float2* wbase = swl + (size_t)oct * 1228800 + lm + (size_t)ob * 3072;

    float2 a0[5], a1[5];
#pragma unroll
    for (int o = 0; o < 5; o++) { a0[o] = make_float2(0.f,0.f); a1[o] = make_float2(0.f,0.f); }

#pragma unroll 4
    for (int i = 0; i < NCH; i++) {
        float2 x0 = __ldg(&g_fd[(size_t)i * NMODE + m]);
        float2 x1 = __ldg(&g_fd[(size_t)(NCH + i) * NMODE + m]);
        const float2* wp = wbase + (size_t)i * 61440;
#pragma unroll
        for (int o = 0; o < 5; o++) {
            float2 w = __ldg(&wp[o * 3072]);
            a0[o].x += w.x * x0.x - w.y * x0.y;
            a0[o].y += w.x * x0.y + w.y * x0.x;
            a1[o].x += w.x * x1.x - w.y * x1.y;
            a1[o].y += w.x * x1.y + w.y * x1.x;
        }
    }
#pragma unroll
    for (int o = 0; o < 5; o++) {
        SE[o * 2 + 0][tid] = a0[o];
        SE[o * 2 + 1][tid] = a1[o];
    }
    __syncthreads();

    {
        int g = tid / 96, rr = tid % 96;
        int kt2 = rr / 16, kz2 = rr % 16;
        int kxky = blockIdx.x * 2 + g;
        int kx2 = kxky >> 4, ky2 = kxky & 15;
        size_t dstoff = (size_t)(kx2 * 6 + kt2) * 256 + ky2 * 16 + kz2;
        int srci = g * 96 + kz2 * 6 + kt2;
#pragma unroll
        for (int row = 0; row < 10; row++) {
            int oo = row >> 1, bb = row & 1;
            g_fe[(size_t)(bb * NCH + ob + oo) * NMODE + dstoff] = SE[row][srci];
        }
    }
}

// ---------------- inv Y + Z, radix-2 imm, contiguous g_fe reads -------------
__global__ void __launch_bounds__(128) k_invZY() {
    __shared__ float2 G[4 * 256];        // [s][ky*16+kz]
    __shared__ float2 H1[4 * 32 * 17];   // [s][y][kz] pad 17
    __shared__ float2 OUT[4 * 32 * 33];  // [s][y][z] pad 33
    int bid = blockIdx.x;
    int sp = bid % 24, bo = bid / 24;
    int b = bo / NCH, o = bo % NCH;
    int tid = threadIdx.x;

    {
        const float4* srcv = (const float4*)(g_fe + (size_t)bo * NMODE + (size_t)sp * 1024);
        float4* dstv = (float4*)G;
#pragma unroll
        for (int q = 0; q < 4; q++) dstv[q * 128 + tid] = srcv[q * 128 + tid];
    }
    __syncthreads();

    // stage invY: 64 threads = (s 4, kz 16); Se/So for y pairs
    if (tid < 64) {
        int s = tid >> 4, kz = tid & 15;
        float2 Se[16], So[16];
#pragma unroll
        for (int y = 0; y < 16; y++) { Se[y] = make_float2(0.f,0.f); So[y] = make_float2(0.f,0.f); }
#pragma unroll
        for (int m = 0; m < 16; m++) {
            const int k = KOF(m);
            float2 g = G[s * 256 + m * 16 + kz];
#pragma unroll
            for (int y = 0; y < 16; y++) {
                const float c = CSI(k*y) * (1.0f/32.0f);
                const float sn = SNI(k*y) * (1.0f/32.0f);
                float2& acc = (m & 1) ? So[y] : Se[y];
                acc.x += g.x * c - g.y * sn;
                acc.y += g.y * c + g.x * sn;
            }
        }
#pragma unroll
        for (int y = 0; y < 16; y++) {
            H1[s * 544 + y * 17 + kz]        = make_float2(Se[y].x + So[y].x, Se[y].y + So[y].y);
            H1[s * 544 + (y + 16) * 17 + kz] = make_float2(Se[y].x - So[y].x, Se[y].y - So[y].y);
        }
    }
    __syncthreads();

    // stage invZ: 128 threads = (s 4, y 32); Se/So for z pairs
    {
        int s = tid >> 5, y = tid & 31;
        float2 Se[16], So[16];
#pragma unroll
        for (int z = 0; z < 16; z++) { Se[z] = make_float2(0.f,0.f); So[z] = make_float2(0.f,0.f); }
#pragma unroll
        for (int m = 0; m < 16; m++) {
            const int k = KOF(m);
            float2 g = H1[s * 544 + y * 17 + m];
#pragma unroll
            for (int z = 0; z < 16; z++) {
                const float c = CSI(k*z) * (1.0f/32.0f);
                const float sn = SNI(k*z) * (1.0f/32.0f);
                float2& acc = (m & 1) ? So[z] : Se[z];
                acc.x += g.x * c - g.y * sn;
                acc.y += g.y * c + g.x * sn;
            }
        }
#pragma unroll
        for (int z = 0; z < 16; z++) {
            OUT[s * 1056 + y * 33 + z]      = make_float2(Se[z].x + So[z].x, Se[z].y + So[z].y);
            OUT[s * 1056 + y * 33 + z + 16] = make_float2(Se[z].x - So[z].x, Se[z].y - So[z].y);
        }
    }
    __syncthreads();

#pragma unroll
    for (int q = 0; q < 8; q++) {
        int yz = q * 128 + tid;
        int y = yz >> 5, z = yz & 31;
        float2 v0 = OUT[0 * 1056 + y * 33 + z];
        float2 v1 = OUT[1 * 1056 + y * 33 + z];
        float2 v2 = OUT[2 * 1056 + y * 33 + z];
        float2 v3 = OUT[3 * 1056 + y * 33 + z];
        float4* dst = (float4*)&g_fb[((size_t)b * 1024 + yz) * 1920 + o * 96 + sp * 4];
        dst[0] = make_float4(v0.x, v0.y, v1.x, v1.y);
        dst[1] = make_float4(v2.x, v2.y, v3.x, v3.y);
    }
}

// ---------------- fused: invX (radix-2 imm) + invT + pointwise + GELU -------
__global__ void __launch_bounds__(256) k_fused(const float* __restrict__ ww,
                                               const float* __restrict__ wb,
                                               int src, int do_gelu) {
    __shared__ __align__(16) float2 Gs[1920];   // [o][kx*6+kt]
    __shared__ float2 E[3840];    // [o][x*6+kt]
    __shared__ float  sww[400];
    __shared__ float  swb[NCH];

    const float* hin  = src ? g_hB : g_hA;
    float*       hout = src ? g_hA : g_hB;

    int b = blockIdx.x >> 10;
    int yz = blockIdx.x & 1023;
    int tid = threadIdx.x;

    int t = tid & 15, x0 = tid >> 4, x1 = x0 + 16;
    size_t p0 = (size_t)x0 * 16384 + (size_t)yz * 16 + t;
    size_t p1 = (size_t)x1 * 16384 + (size_t)yz * 16 + t;
    float hv0[NCH], hv1[NCH];
#pragma unroll
    for (int i = 0; i < NCH; i++) {
        hv0[i] = hin[(size_t)(b * NCH + i) * NSP + p0];
        hv1[i] = hin[(size_t)(b * NCH + i) * NSP + p1];
    }

    {
        const float4* srcv = (const float4*)&g_fb[((size_t)b * 1024 + yz) * 1920];
        float4* dstv = (float4*)Gs;
        for (int q = tid; q < 960; q += 256) dstv[q] = srcv[q];
    }
    for (int q = tid; q < 400; q += 256) sww[q] = ww[q];
    if (tid < NCH) swb[tid] = wb[tid];
    __syncthreads();

    if (tid < 120) {
        int o = tid / 6, kt = tid % 6;
        float2 Se[16], So[16];
#pragma unroll
        for (int x = 0; x < 16; x++) { Se[x] = make_float2(0.f,0.f); So[x] = make_float2(0.f,0.f); }
#pragma unroll
        for (int m = 0; m < 16; m++) {
            const int k = KOF(m);
            float2 g = Gs[o * 96 + m * 6 + kt];
#pragma unroll
            for (int x = 0; x < 16; x++) {
                const float c = CSI(k*x) * (1.0f/32.0f);
                const float sn = SNI(k*x) * (1.0f/32.0f);
                float2& acc = (m & 1) ? So[x] : Se[x];
                acc.x += g.x * c - g.y * sn;
                acc.y += g.y * c + g.x * sn;
            }
        }
#pragma unroll
        for (int x = 0; x < 16; x++) {
            E[o * 192 + x * 6 + kt]        = make_float2(Se[x].x + So[x].x, Se[x].y + So[x].y);
            E[o * 192 + (x + 16) * 6 + kt] = make_float2(Se[x].x - So[x].x, Se[x].y - So[x].y);
        }
    }
    __syncthreads();

    {
        float2 wt[6];
#pragma unroll
        for (int k = 0; k < 6; k++) wt[k] = d_invT[t * 6 + k];

#pragma unroll 4
        for (int o = 0; o < NCH; o++) {
            float acc0 = swb[o], acc1 = acc0;
#pragma unroll
            for (int i = 0; i < NCH; i++) {
                float w = sww[o * NCH + i];
                acc0 += w * hv0[i];
                acc1 += w * hv1[i];
            }
            const float2* eo0 = &E[o * 192 + x0 * 6];
            const float2* eo1 = &E[o * 192 + x1 * 6];
            float s0 = 0.f, s1 = 0.f;
#pragma unroll
            for (int k = 0; k < 6; k++) {
                s0 += eo0[k].x * wt[k].x - eo0[k].y * wt[k].y;
                s1 += eo1[k].x * wt[k].x - eo1[k].y * wt[k].y;
            }
            float v0 = acc0 + s0, v1 = acc1 + s1;
            if (do_gelu) { v0 = gelu_exact(v0); v1 = gelu_exact(v1); }
            hout[(size_t)(b * NCH + o) * NSP + p0] = v0;
            hout[(size_t)(b * NCH + o) * NSP + p1] = v1;
        }
    }
}

// ---------------- fused LAST layer + head: no hB round-trip -----------------
__global__ void __launch_bounds__(256) k_fused_head(const float* __restrict__ ww,
                                                    const float* __restrict__ wb,
                                                    const float* __restrict__ fc1w,
                                                    const float* __restrict__ fc1b,
                                                    const float* __restrict__ fc2w,
                                                    const float* __restrict__ fc2b,
                                                    float* __restrict__ out,
                                                    int src) {
    __shared__ __align__(16) float2 Gs[1920];   // reused for w1 after invX
    __shared__ float2 E[3840];
    __shared__ float  sww[400];
    __shared__ float  swb[NCH];
    __shared__ float  b1s[128], w2s[128];

    const float* hin = src ? g_hB : g_hA;

    int b = blockIdx.x >> 10;
    int yz = blockIdx.x & 1023;
    int tid = threadIdx.x;

    int t = tid & 15, x0 = tid >> 4, x1 = x0 + 16;
    size_t p0 = (size_t)x0 * 16384 + (size_t)yz * 16 + t;
    size_t p1 = (size_t)x1 * 16384 + (size_t)yz * 16 + t;
    float hv0[NCH], hv1[NCH];
#pragma unroll
    for (int i = 0; i < NCH; i++) {
        hv0[i] = hin[(size_t)(b * NCH + i) * NSP + p0];
        hv1[i] = hin[(size_t)(b * NCH + i) * NSP + p1];
    }

    {
        const float4* srcv = (const float4*)&g_fb[((size_t)b * 1024 + yz) * 1920];
        float4* dstv = (float4*)Gs;
        for (int q = tid; q < 960; q += 256) dstv[q] = srcv[q];
    }
    for (int q = tid; q < 400; q += 256) sww[q] = ww[q];
    if (tid < NCH) swb[tid] = wb[tid];
    if (tid < 128) { b1s[tid] = fc1b[tid]; w2s[tid] = fc2w[tid]; }
    __syncthreads();

    // stage invX: 120 threads = (o 20, kt 6)
    if (tid < 120) {
        int o = tid / 6, kt = tid % 6;
        float2 Se[16], So[16];
#pragma unroll
        for (int x = 0; x < 16; x++) { Se[x] = make_float2(0.f,0.f); So[x] = make_float2(0.f,0.f); }
#pragma unroll
        for (int m = 0; m < 16; m++) {
            const int k = KOF(m);
            float2 g = Gs[o * 96 + m * 6 + kt];
#pragma unroll
            for (int x = 0; x < 16; x++) {
                const float c = CSI(k*x) * (1.0f/32.0f);
                const float sn = SNI(k*x) * (1.0f/32.0f);
                float2& acc = (m & 1) ? So[x] : Se[x];
                acc.x += g.x * c - g.y * sn;
                acc.y += g.y * c + g.x * sn;
            }
        }
#pragma unroll
        for (int x = 0; x < 16; x++) {
            E[o * 192 + x * 6 + kt]        = make_float2(Se[x].x + So[x].x, Se[x].y + So[x].y);
            E[o * 192 + (x + 16) * 6 + kt] = make_float2(Se[x].x - So[x].x, Se[x].y - So[x].y);
        }
    }
    __syncthreads();

    // Gs region now free: stage fc1 weights (2560 floats) into it
    float* w1s = (float*)Gs;
    for (int q = tid; q < NCH * 128; q += 256) w1s[q] = fc1w[q];
    __syncthreads();

    // stage 2: compute final h per point into registers (no gelu at l=3)
    float ho0[NCH], ho1[NCH];
    {
        float2 wt[6];
#pragma unroll
        for (int k = 0; k < 6; k++) wt[k] = d_invT[t * 6 + k];

#pragma unroll 4
        for (int o = 0; o < NCH; o++) {
            float acc0 = swb[o], acc1 = acc0;
#pragma unroll
            for (int i = 0; i < NCH; i++) {
                float w = sww[o * NCH + i];
                acc0 += w * hv0[i];
                acc1 += w * hv1[i];
            }
            const float2* eo0 = &E[o * 192 + x0 * 6];
            const float2* eo1 = &E[o * 192 + x1 * 6];
            float s0 = 0.f, s1 = 0.f;
#pragma unroll
            for (int k = 0; k < 6; k++) {
                s0 += eo0[k].x * wt[k].x - eo0[k].y * wt[k].y;
                s1 += eo1[k].x * wt[k].x - eo1[k].y * wt[k].y;
            }
            ho0[o] = acc0 + s0;
            ho1[o] = acc1 + s1;
        }
    }

    // head: fc1 (20->128) + GELU + fc2 (128->1)
    float acc0 = __ldg(&fc2b[0]), acc1 = acc0;
#pragma unroll 4
    for (int j = 0; j < 128; j++) {
        float a0 = b1s[j], a1 = b1s[j];
#pragma unroll
        for (int i = 0; i < NCH; i++) {
            float w = w1s[i * 128 + j];
            a0 += ho0[i] * w;
            a1 += ho1[i] * w;
        }
        a0 = gelu_exact(a0); a1 = gelu_exact(a1);
        float w2j = w2s[j];
        acc0 += a0 * w2j; acc1 += a1 * w2j;
    }
    out[(size_t)b * NSP + p0] = acc0;
    out[(size_t)b * NSP + p1] = acc1;
}

// ---------------- launch ----------------------------------------------------
extern "C" void kernel_launch(void* const* d_in, const int* in_sizes, int n_in,
                              void* d_out, int out_size) {
    const float* x     = (const float*)d_in[0];
    const float* fc0_w = (const float*)d_in[1];
    const float* fc0_b = (const float*)d_in[2];
    const float* sw    = (const float*)d_in[3];
    const float* ww    = (const float*)d_in[4];
    const float* wb    = (const float*)d_in[5];
    const float* fc1_w = (const float*)d_in[6];
    const float* fc1_b = (const float*)d_in[7];
    const float* fc2_w = (const float*)d_in[8];
    const float* fc2_b = (const float*)d_in[9];
    float* out = (float*)d_out;

    k_init<<<1, 128>>>();
    k_lift<<<1024, 256>>>(x, fc0_w, fc0_b);

    int src = 0;
    for (int l = 0; l < 4; l++) {
        k_fwdTZ<<<NB*NCH*64, 128>>>(src);
        k_fwdYX<<<NB*NCH*24, 128>>>();
        const float2* swl = (const float2*)sw + (size_t)l * 9830400;
        dim3 mg(128, 4);
        k_mult<<<mg, 192>>>(swl);
        k_invZY<<<NB*NCH*24, 128>>>();
        if (l < 3) {
            k_fused<<<NB*1024, 256>>>(ww + l * 400, wb + l * NCH, src, 1);
            src ^= 1;
        } else {
            k_fused_head<<<NB*1024, 256>>>(ww + l * 400, wb + l * NCH,
                                           fc1_w, fc1_b, fc2_w, fc2_b, out, src);
        }
    }
}

// round 17
// speedup vs baseline: 1.1439x; 1.0044x over previous
#include <cuda_runtime.h>
#include <math.h>

// ---------------- static scratch ----------------
#define NSP 524288            // 32*32*32*16 points per (b,c)
#define NCH 20
#define NB  2
#define NMODE 24576           // 16*16*16*6 kept modes

__device__ float  g_hA[NB*NCH*NSP];          // 84 MB
__device__ float  g_hB[NB*NCH*NSP];          // 84 MB
__device__ float2 g_fa[NB*NCH*96*1024];      // S1 [bc][kz*6+kt][x*32+y]
__device__ float2 g_fb[NB*1024*1920];        // S2 [b][y*32+z][o*96 + kx*6+kt]  (yz-major)
__device__ float2 g_fd[NB*NCH*NMODE];        // x_ft  (m = (kx*16+ky)*96 + kz*6+kt)
__device__ float2 g_fe[NB*NCH*NMODE];        // out_ft SLAB-MAJOR: [(kx*6+kt)*256 + ky*16+kz]

// cos(pi*j/16); sin(pi*j/16) = CSX[(j+24)&31]
__device__ static const float CSX[32] = {
     1.000000000f,  0.980785280f,  0.923879533f,  0.831469612f,
     0.707106781f,  0.555570233f,  0.382683432f,  0.195090322f,
     0.000000000f, -0.195090322f, -0.382683432f, -0.555570233f,
    -0.707106781f, -0.831469612f, -0.923879533f, -0.980785280f,
    -1.000000000f, -0.980785280f, -0.923879533f, -0.831469612f,
    -0.707106781f, -0.555570233f, -0.382683432f, -0.195090322f,
     0.000000000f,  0.195090322f,  0.382683432f,  0.555570233f,
     0.707106781f,  0.831469612f,  0.923879533f,  0.980785280f };

#define CSI(p) CSX[(p) & 31]
#define SNI(p) CSX[((p) + 24) & 31]
#define KOF(m) ((m) + ((m) >= 8 ? 16 : 0))

__device__ float2 d_invT[96];   // [t(16)][k(6)] ((k==0?1:2)/16)*(cos,sin)(+2pi k t/16)

__device__ __forceinline__ float gelu_exact(float v) {
    return 0.5f * v * (1.0f + erff(v * 0.70710678118654752f));
}

__global__ void k_init() {
    int tid = threadIdx.x;
    if (tid < 96) {
        int t2 = tid / 6, k2 = tid % 6;
        int ph2 = (k2 * t2) & 15;
        float wk = (k2 == 0 ? 1.0f : 2.0f) * (1.0f/16.0f);
        float s2, c2; sincospif((float)ph2 / 8.0f, &s2, &c2);
        d_invT[tid] = make_float2(wk * c2, wk * s2);
    }
}

// ---------------- lift: 4 points/thread, float4 stores ----------------------
__global__ void __launch_bounds__(256) k_lift(const float* __restrict__ x,
                                              const float* __restrict__ w,
                                              const float* __restrict__ bias) {
    int tid = blockIdx.x * blockDim.x + threadIdx.x;   // NB*NSP/4 threads
    if (tid >= NB * NSP / 4) return;
    int b = tid / (NSP / 4), r = tid % (NSP / 4);
    size_t p4 = (size_t)r * 4;

    float xi[4][5];
    const float* xs = x + ((size_t)b * NSP + p4) * 5;
#pragma unroll
    for (int q = 0; q < 4; q++)
#pragma unroll
        for (int i = 0; i < 5; i++) xi[q][i] = xs[q * 5 + i];

#pragma unroll
    for (int c = 0; c < NCH; c++) {
        float bc = __ldg(&bias[c]);
        float4 a;
        float* av = (float*)&a;
#pragma unroll
        for (int q = 0; q < 4; q++) {
            float s = bc;
#pragma unroll
            for (int i = 0; i < 5; i++) s += xi[q][i] * __ldg(&w[i * NCH + c]);
            av[q] = s;
        }
        *(float4*)&g_hA[(size_t)(b * NCH + c) * NSP + p4] = a;
    }
}

// ---------------- fwd T (16->6) + Z (32->16), radix-2 imm -------------------
__global__ void __launch_bounds__(128) k_fwdTZ(int src) {
    __shared__ float2 st[6 * 16 * 33];            // [kt][yl][z] pad 33
    const float* h = src ? g_hB : g_hA;
    int bid = blockIdx.x;
    int yh = bid & 1, x = (bid >> 1) & 31, bc = bid >> 6;
    int tid = threadIdx.x;

#pragma unroll
    for (int q = 0; q < 4; q++) {
        int p = q * 128 + tid;
        int yl = p >> 5, z = p & 31;
        const float4* src4 = (const float4*)(h + (size_t)bc * NSP + x * 16384
                                             + (yh * 16 + yl) * 512 + z * 16);
        float v[16];
#pragma unroll
        for (int r = 0; r < 4; r++) {
            float4 f = src4[r];
            v[r*4+0]=f.x; v[r*4+1]=f.y; v[r*4+2]=f.z; v[r*4+3]=f.w;
        }
        float ue[8], uo[8];
#pragma unroll
        for (int t = 0; t < 8; t++) { ue[t] = v[t] + v[t+8]; uo[t] = v[t] - v[t+8]; }
#pragma unroll
        for (int k = 0; k < 6; k++) {
            const float* wsrc = (k & 1) ? uo : ue;
            float ax = 0.f, ay = 0.f;
#pragma unroll
            for (int t = 0; t < 8; t++) {
                ax += wsrc[t] * CSI(2*k*t);
                ay -= wsrc[t] * SNI(2*k*t);
            }
            st[(k * 16 + yl) * 33 + z] = make_float2(ax, ay);
        }
    }
    __syncthreads();

    // stage Z: 96 threads = (kt 6, yl 16); radix-2, 16 accs
    if (tid < 96) {
        int kt = tid >> 4, yl = tid & 15;
        float2 A[16];
#pragma unroll
        for (int m = 0; m < 16; m++) A[m] = make_float2(0.f, 0.f);
#pragma unroll
        for (int zp = 0; zp < 16; zp++) {
            float2 g0 = st[(kt * 16 + yl) * 33 + zp];
            float2 g1 = st[(kt * 16 + yl) * 33 + zp + 16];
            float2 u = make_float2(g0.x + g1.x, g0.y + g1.y);
            float2 v = make_float2(g0.x - g1.x, g0.y - g1.y);
#pragma unroll
            for (int mm = 0; mm < 8; mm++) {
                const int ke = KOF(2*mm);
                A[2*mm].x   += u.x * CSI(ke*zp) + u.y * SNI(ke*zp);
                A[2*mm].y   += u.y * CSI(ke*zp) - u.x * SNI(ke*zp);
                const int ko = KOF(2*mm+1);
                A[2*mm+1].x += v.x * CSI(ko*zp) + v.y * SNI(ko*zp);
                A[2*mm+1].y += v.y * CSI(ko*zp) - v.x * SNI(ko*zp);
            }
        }
#pragma unroll
        for (int m = 0; m < 16; m++)
            g_fa[((size_t)bc * 96 + m * 6 + kt) * 1024 + x * 32 + yh * 16 + yl] = A[m];
    }
}

// ---------------- fwd Y + X, radix-2 imm, 4 slabs / 128 threads -------------
__global__ void __launch_bounds__(128) k_fwdYX() {
    __shared__ float2 P[4 * 32 * 33];   // [s][x][y] pad 33; reused as OUT[1024]
    int bid = blockIdx.x;
    int sp = bid % 24, bc = bid / 24;
    int tid = threadIdx.x;
    const float2* s1 = g_fa + ((size_t)bc * 96 + sp * 4) * 1024;
#pragma unroll
    for (int q = 0; q < 32; q++) {
        int u = q * 128 + tid;
        int s = u >> 10, r = u & 1023;
        P[s * 1056 + (r >> 5) * 33 + (r & 31)] = s1[u];
    }
    __syncthreads();

    // stage Y: (s 4, x 32) = 128; radix-2 over y, 16 ky accs; in-place write
    {
        int s = tid >> 5, x = tid & 31;
        float2 A[16];
#pragma unroll
        for (int m = 0; m < 16; m++) A[m] = make_float2(0.f, 0.f);
#pragma unroll
        for (int yp = 0; yp < 16; yp++) {
            float2 g0 = P[s * 1056 + x * 33 + yp];
            float2 g1 = P[s * 1056 + x * 33 + yp + 16];
            float2 u = make_float2(g0.x + g1.x, g0.y + g1.y);
            float2 v = make_float2(g0.x - g1.x, g0.y - g1.y);
#pragma unroll
            for (int mm = 0; mm < 8; mm++) {
                const int ke = KOF(2*mm);
                A[2*mm].x   += u.x * CSI(ke*yp) + u.y * SNI(ke*yp);
                A[2*mm].y   += u.y * CSI(ke*yp) - u.x * SNI(ke*yp);
                const int ko = KOF(2*mm+1);
                A[2*mm+1].x += v.x * CSI(ko*yp) + v.y * SNI(ko*yp);
                A[2*mm+1].y += v.y * CSI(ko*yp) - v.x * SNI(ko*yp);
            }
        }
#pragma unroll
        for (int m = 0; m < 16; m++) P[s * 1056 + x * 33 + m] = A[m];
    }
    __syncthreads();

    // stage X: (s 4, ky 16, par 2) = 128; mode-parity split with twiddle fold
    {
        int s = tid >> 5;
        int r = tid & 31; int ky = r >> 1; int par = r & 1;
        float2 A[8];
#pragma unroll
        for (int mm = 0; mm < 8; mm++) A[mm] = make_float2(0.f, 0.f);
#pragma unroll
        for (int xp = 0; xp < 16; xp++) {
            float2 g0 = P[s * 1056 + xp * 33 + ky];
            float2 g1 = P[s * 1056 + (xp + 16) * 33 + ky];
            float2 w;
            if (par) {
                float vx = g0.x - g1.x, vy = g0.y - g1.y;
                w.x = vx * CSI(xp) + vy * SNI(xp);
                w.y = vy * CSI(xp) - vx * SNI(xp);
            } else {
                w.x = g0.x + g1.x; w.y = g0.y + g1.y;
            }
#pragma unroll
            for (int mm = 0; mm < 8; mm++) {
                const int ke = KOF(2*mm);
                A[mm].x += w.x * CSI(ke*xp) + w.y * SNI(ke*xp);
                A[mm].y += w.y * CSI(ke*xp) - w.x * SNI(ke*xp);
            }
        }
        __syncthreads();               // all P reads done; reuse P as OUT
        float2* OUTS = P;              // OUT[(kx*16+ky)*4 + s]
#pragma unroll
        for (int mm = 0; mm < 8; mm++) {
            int m = 2 * mm + par;      // m == kx
            OUTS[(m * 16 + ky) * 4 + s] = A[mm];
        }
    }
    __syncthreads();

    // flush: per (kx,ky) write 4 consecutive kk (= sp*4..sp*4+3) as 2 float4
#pragma unroll
    for (int j = 0; j < 2; j++) {
        int u = tid + j * 128;        // u = kx*16+ky
        float2 v0 = P[u * 4 + 0];
        float2 v1 = P[u * 4 + 1];
        float2 v2 = P[u * 4 + 2];
        float2 v3 = P[u * 4 + 3];
        float4* dst = (float4*)&g_fd[(size_t)bc * NMODE + (size_t)u * 96 + sp * 4];
        dst[0] = make_float4(v0.x, v0.y, v1.x, v1.y);
        dst[1] = make_float4(v2.x, v2.y, v3.x, v3.y);
    }
}

// ---------------- spectral channel mix: 2 outputs/thread, high occupancy ----
// grid (128, 10): blockIdx.y selects 2 output channels
__global__ void __launch_bounds__(192) k_mult(const float2* __restrict__ swl) {
    __shared__ float2 SE[4][192];       // [o_local*2 + b][tid]  (6 KB)
    int tid = threadIdx.x;
    int m = blockIdx.x * 192 + tid;     // grid.x = 128
    int ob = blockIdx.y * 2;
    int kt = m % 6; int r = m / 6;
    int kz = r & 15, ky = (r >> 4) & 15, kx = (r >> 8) & 15;
    int oct = ((kx >> 3) << 2) | ((ky >> 3) << 1) | (kz >> 3);
    int lm = (((kx & 7) * 8 + (ky & 7)) * 8 + (kz & 7)) * 6 + kt;
    const float2* wbase = swl + (size_t)oct * 1228800 + lm + (size_t)ob * 3072;

    float2 a0[2], a1[2];
#pragma unroll
    for (int o = 0; o < 2; o++) { a0[o] = make_float2(0.f,0.f); a1[o] = make_float2(0.f,0.f); }

#pragma unroll 4
    for (int i = 0; i < NCH; i++) {
        float2 x0 = __ldg(&g_fd[(size_t)i * NMODE + m]);
        float2 x1 = __ldg(&g_fd[(size_t)(NCH + i) * NMODE + m]);
        const float2* wp = wbase + (size_t)i * 61440;
#pragma unroll
        for (int o = 0; o < 2; o++) {
            float2 w = __ldg(&wp[o * 3072]);
            a0[o].x += w.x * x0.x - w.y * x0.y;
            a0[o].y += w.x * x0.y + w.y * x0.x;
            a1[o].x += w.x * x1.x - w.y * x1.y;
            a1[o].y += w.x * x1.y + w.y * x1.x;
        }
    }
#pragma unroll
    for (int o = 0; o < 2; o++) {
        SE[o * 2 + 0][tid] = a0[o];
        SE[o * 2 + 1][tid] = a1[o];
    }
    __syncthreads();

    {
        int g = tid / 96, rr = tid % 96;
        int kt2 = rr / 16, kz2 = rr % 16;
        int kxky = blockIdx.x * 2 + g;
        int kx2 = kxky >> 4, ky2 = kxky & 15;
        size_t dstoff = (size_t)(kx2 * 6 + kt2) * 256 + ky2 * 16 + kz2;
        int srci = g * 96 + kz2 * 6 + kt2;
#pragma unroll
        for (int row = 0; row < 4; row++) {
            int oo = row >> 1, bb = row & 1;
            g_fe[(size_t)(bb * NCH + ob + oo) * NMODE + dstoff] = SE[row][srci];
        }
    }
}

// ---------------- inv Y + Z, radix-2 imm, contiguous g_fe reads -------------
__global__ void __launch_bounds__(128) k_invZY() {
    __shared__ float2 G[4 * 256];        // [s][ky*16+kz]
    __shared__ float2 H1[4 * 32 * 17];   // [s][y][kz] pad 17
    __shared__ float2 OUT[4 * 32 * 33];  // [s][y][z] pad 33
    int bid = blockIdx.x;
    int sp = bid % 24, bo = bid / 24;
    int b = bo / NCH, o = bo % NCH;
    int tid = threadIdx.x;

    {
        const float4* srcv = (const float4*)(g_fe + (size_t)bo * NMODE + (size_t)sp * 1024);
        float4* dstv = (float4*)G;
#pragma unroll
        for (int q = 0; q < 4; q++) dstv[q * 128 + tid] = srcv[q * 128 + tid];
    }
    __syncthreads();

    // stage invY: 64 threads = (s 4, kz 16); Se/So for y pairs
    if (tid < 64) {
        int s = tid >> 4, kz = tid & 15;
        float2 Se[16], So[16];
#pragma unroll
        for (int y = 0; y < 16; y++) { Se[y] = make_float2(0.f,0.f); So[y] = make_float2(0.f,0.f); }
#pragma unroll
        for (int m = 0; m < 16; m++) {
            const int k = KOF(m);
            float2 g = G[s * 256 + m * 16 + kz];
#pragma unroll
            for (int y = 0; y < 16; y++) {
                const float c = CSI(k*y) * (1.0f/32.0f);
                const float sn = SNI(k*y) * (1.0f/32.0f);
                float2& acc = (m & 1) ? So[y] : Se[y];
                acc.x += g.x * c - g.y * sn;
                acc.y += g.y * c + g.x * sn;
            }
        }
#pragma unroll
        for (int y = 0; y < 16; y++) {
            H1[s * 544 + y * 17 + kz]        = make_float2(Se[y].x + So[y].x, Se[y].y + So[y].y);
            H1[s * 544 + (y + 16) * 17 + kz] = make_float2(Se[y].x - So[y].x, Se[y].y - So[y].y);
        }
    }
    __syncthreads();

    // stage invZ: 128 threads = (s 4, y 32); Se/So for z pairs
    {
        int s = tid >> 5, y = tid & 31;
        float2 Se[16], So[16];
#pragma unroll
        for (int z = 0; z < 16; z++) { Se[z] = make_float2(0.f,0.f); So[z] = make_float2(0.f,0.f); }
#pragma unroll
        for (int m = 0; m < 16; m++) {
            const int k = KOF(m);
            float2 g = H1[s * 544 + y * 17 + m];
#pragma unroll
            for (int z = 0; z < 16; z++) {
                const float c = CSI(k*z) * (1.0f/32.0f);
                const float sn = SNI(k*z) * (1.0f/32.0f);
                float2& acc = (m & 1) ? So[z] : Se[z];
                acc.x += g.x * c - g.y * sn;
                acc.y += g.y * c + g.x * sn;
            }
        }
#pragma unroll
        for (int z = 0; z < 16; z++) {
            OUT[s * 1056 + y * 33 + z]      = make_float2(Se[z].x + So[z].x, Se[z].y + So[z].y);
            OUT[s * 1056 + y * 33 + z + 16] = make_float2(Se[z].x - So[z].x, Se[z].y - So[z].y);
        }
    }
    __syncthreads();

#pragma unroll
    for (int q = 0; q < 8; q++) {
        int yz = q * 128 + tid;
        int y = yz >> 5, z = yz & 31;
        float2 v0 = OUT[0 * 1056 + y * 33 + z];
        float2 v1 = OUT[1 * 1056 + y * 33 + z];
        float2 v2 = OUT[2 * 1056 + y * 33 + z];
        float2 v3 = OUT[3 * 1056 + y * 33 + z];
        float4* dst = (float4*)&g_fb[((size_t)b * 1024 + yz) * 1920 + o * 96 + sp * 4];
        dst[0] = make_float4(v0.x, v0.y, v1.x, v1.y);
        dst[1] = make_float4(v2.x, v2.y, v3.x, v3.y);
    }
}

// ---------------- fused: invX (radix-2 imm) + invT + pointwise + GELU -------
__global__ void __launch_bounds__(256) k_fused(const float* __restrict__ ww,
                                               const float* __restrict__ wb,
                                               int src, int do_gelu) {
    __shared__ __align__(16) float2 Gs[1920];   // [o][kx*6+kt]
    __shared__ float2 E[3840];    // [o][x*6+kt]
    __shared__ float  sww[400];
    __shared__ float  swb[NCH];

    const float* hin  = src ? g_hB : g_hA;
    float*       hout = src ? g_hA : g_hB;

    int b = blockIdx.x >> 10;
    int yz = blockIdx.x & 1023;
    int tid = threadIdx.x;

    int t = tid & 15, x0 = tid >> 4, x1 = x0 + 16;
    size_t p0 = (size_t)x0 * 16384 + (size_t)yz * 16 + t;
    size_t p1 = (size_t)x1 * 16384 + (size_t)yz * 16 + t;
    float hv0[NCH], hv1[NCH];
#pragma unroll
    for (int i = 0; i < NCH; i++) {
        hv0[i] = hin[(size_t)(b * NCH + i) * NSP + p0];
        hv1[i] = hin[(size_t)(b * NCH + i) * NSP + p1];
    }

    {
        const float4* srcv = (const float4*)&g_fb[((size_t)b * 1024 + yz) * 1920];
        float4* dstv = (float4*)Gs;
        for (int q = tid; q < 960; q += 256) dstv[q] = srcv[q];
    }
    for (int q = tid; q < 400; q += 256) sww[q] = ww[q];
    if (tid < NCH) swb[tid] = wb[tid];
    __syncthreads();

    if (tid < 120) {
        int o = tid / 6, kt = tid % 6;
        float2 Se[16], So[16];
#pragma unroll
        for (int x = 0; x < 16; x++) { Se[x] = make_float2(0.f,0.f); So[x] = make_float2(0.f,0.f); }
#pragma unroll
        for (int m = 0; m < 16; m++) {
            const int k = KOF(m);
            float2 g = Gs[o * 96 + m * 6 + kt];
#pragma unroll
            for (int x = 0; x < 16; x++) {
                const float c = CSI(k*x) * (1.0f/32.0f);
                const float sn = SNI(k*x) * (1.0f/32.0f);
                float2& acc = (m & 1) ? So[x] : Se[x];
                acc.x += g.x * c - g.y * sn;
                acc.y += g.y * c + g.x * sn;
            }
        }
#pragma unroll
        for (int x = 0; x < 16; x++) {
            E[o * 192 + x * 6 + kt]        = make_float2(Se[x].x + So[x].x, Se[x].y + So[x].y);
            E[o * 192 + (x + 16) * 6 + kt] = make_float2(Se[x].x - So[x].x, Se[x].y - So[x].y);
        }
    }
    __syncthreads();

    {
        float2 wt[6];
#pragma unroll
        for (int k = 0; k < 6; k++) wt[k] = d_invT[t * 6 + k];

#pragma unroll 4
        for (int o = 0; o < NCH; o++) {
            float acc0 = swb[o], acc1 = acc0;
#pragma unroll
            for (int i = 0; i < NCH; i++) {
                float w = sww[o * NCH + i];
                acc0 += w * hv0[i];
                acc1 += w * hv1[i];
            }
            const float2* eo0 = &E[o * 192 + x0 * 6];
            const float2* eo1 = &E[o * 192 + x1 * 6];
            float s0 = 0.f, s1 = 0.f;
#pragma unroll
            for (int k = 0; k < 6; k++) {
                s0 += eo0[k].x * wt[k].x - eo0[k].y * wt[k].y;
                s1 += eo1[k].x * wt[k].x - eo1[k].y * wt[k].y;
            }
            float v0 = acc0 + s0, v1 = acc1 + s1;
            if (do_gelu) { v0 = gelu_exact(v0); v1 = gelu_exact(v1); }
            hout[(size_t)(b * NCH + o) * NSP + p0] = v0;
            hout[(size_t)(b * NCH + o) * NSP + p1] = v1;
        }
    }
}

// ---------------- fused LAST layer + head: no hB round-trip -----------------
__global__ void __launch_bounds__(256) k_fused_head(const float* __restrict__ ww,
                                                    const float* __restrict__ wb,
                                                    const float* __restrict__ fc1w,
                                                    const float* __restrict__ fc1b,
                                                    const float* __restrict__ fc2w,
                                                    const float* __restrict__ fc2b,
                                                    float* __restrict__ out,
                                                    int src) {
    __shared__ __align__(16) float2 Gs[1920];   // reused for w1 after invX
    __shared__ float2 E[3840];
    __shared__ float  sww[400];
    __shared__ float  swb[NCH];
    __shared__ float  b1s[128], w2s[128];

    const float* hin = src ? g_hB : g_hA;

    int b = blockIdx.x >> 10;
    int yz = blockIdx.x & 1023;
    int tid = threadIdx.x;

    int t = tid & 15, x0 = tid >> 4, x1 = x0 + 16;
    size_t p0 = (size_t)x0 * 16384 + (size_t)yz * 16 + t;
    size_t p1 = (size_t)x1 * 16384 + (size_t)yz * 16 + t;
    float hv0[NCH], hv1[NCH];
#pragma unroll
    for (int i = 0; i < NCH; i++) {
        hv0[i] = hin[(size_t)(b * NCH + i) * NSP + p0];
        hv1[i] = hin[(size_t)(b * NCH + i) * NSP + p1];
    }

    {
        const float4* srcv = (const float4*)&g_fb[((size_t)b * 1024 + yz) * 1920];
        float4* dstv = (float4*)Gs;
        for (int q = tid; q < 960; q += 256) dstv[q] = srcv[q];
    }
    for (int q = tid; q < 400; q += 256) sww[q] = ww[q];
    if (tid < NCH) swb[tid] = wb[tid];
    if (tid < 128) { b1s[tid] = fc1b[tid]; w2s[tid] = fc2w[tid]; }
    __syncthreads();

    // stage invX: 120 threads = (o 20, kt 6)
    if (tid < 120) {
        int o = tid / 6, kt = tid % 6;
        float2 Se[16], So[16];
#pragma unroll
        for (int x = 0; x < 16; x++) { Se[x] = make_float2(0.f,0.f); So[x] = make_float2(0.f,0.f); }
#pragma unroll
        for (int m = 0; m < 16; m++) {
            const int k = KOF(m);
            float2 g = Gs[o * 96 + m * 6 + kt];
#pragma unroll
            for (int x = 0; x < 16; x++) {
                const float c = CSI(k*x) * (1.0f/32.0f);
                const float sn = SNI(k*x) * (1.0f/32.0f);
                float2& acc = (m & 1) ? So[x] : Se[x];
                acc.x += g.x * c - g.y * sn;
                acc.y += g.y * c + g.x * sn;
            }
        }
#pragma unroll
        for (int x = 0; x < 16; x++) {
            E[o * 192 + x * 6 + kt]        = make_float2(Se[x].x + So[x].x, Se[x].y + So[x].y);
            E[o * 192 + (x + 16) * 6 + kt] = make_float2(Se[x].x - So[x].x, Se[x].y - So[x].y);
        }
    }
    __syncthreads();

    // Gs region now free: stage fc1 weights (2560 floats) into it
    float* w1s = (float*)Gs;
    for (int q = tid; q < NCH * 128; q += 256) w1s[q] = fc1w[q];
    __syncthreads();

    // stage 2: compute final h per point into registers (no gelu at l=3)
    float ho0[NCH], ho1[NCH];
    {
        float2 wt[6];
#pragma unroll
        for (int k = 0; k < 6; k++) wt[k] = d_invT[t * 6 + k];

#pragma unroll 4
        for (int o = 0; o < NCH; o++) {
            float acc0 = swb[o], acc1 = acc0;
#pragma unroll
            for (int i = 0; i < NCH; i++) {
                float w = sww[o * NCH + i];
                acc0 += w * hv0[i];
                acc1 += w * hv1[i];
            }
            const float2* eo0 = &E[o * 192 + x0 * 6];
            const float2* eo1 = &E[o * 192 + x1 * 6];
            float s0 = 0.f, s1 = 0.f;
#pragma unroll
            for (int k = 0; k < 6; k++) {
                s0 += eo0[k].x * wt[k].x - eo0[k].y * wt[k].y;
                s1 += eo1[k].x * wt[k].x - eo1[k].y * wt[k].y;
            }
            ho0[o] = acc0 + s0;
            ho1[o] = acc1 + s1;
        }
    }

    // head: fc1 (20->128) + GELU + fc2 (128->1)
    float acc0 = __ldg(&fc2b[0]), acc1 = acc0;
#pragma unroll 4
    for (int j = 0; j < 128; j++) {
        float a0 = b1s[j], a1 = b1s[j];
#pragma unroll
        for (int i = 0; i < NCH; i++) {
            float w = w1s[i * 128 + j];
            a0 += ho0[i] * w;
            a1 += ho1[i] * w;
        }
        a0 = gelu_exact(a0); a1 = gelu_exact(a1);
        float w2j = w2s[j];
        acc0 += a0 * w2j; acc1 += a1 * w2j;
    }
    out[(size_t)b * NSP + p0] = acc0;
    out[(size_t)b * NSP + p1] = acc1;
}

// ---------------- launch ----------------------------------------------------
extern "C" void kernel_launch(void* const* d_in, const int* in_sizes, int n_in,
                              void* d_out, int out_size) {
    const float* x     = (const float*)d_in[0];
    const float* fc0_w = (const float*)d_in[1];
    const float* fc0_b = (const float*)d_in[2];
    const float* sw    = (const float*)d_in[3];
    const float* ww    = (const float*)d_in[4];
    const float* wb    = (const float*)d_in[5];
    const float* fc1_w = (const float*)d_in[6];
    const float* fc1_b = (const float*)d_in[7];
    const float* fc2_w = (const float*)d_in[8];
    const float* fc2_b = (const float*)d_in[9];
    float* out = (float*)d_out;

    k_init<<<1, 128>>>();
    k_lift<<<1024, 256>>>(x, fc0_w, fc0_b);

    int src = 0;
    for (int l = 0; l < 4; l++) {
        k_fwdTZ<<<NB*NCH*64, 128>>>(src);
        k_fwdYX<<<NB*NCH*24, 128>>>();
        const float2* swl = (const float2*)sw + (size_t)l * 9830400;
        dim3 mg(128, 10);
        k_mult<<<mg, 192>>>(swl);
        k_invZY<<<NB*NCH*24, 128>>>();
        if (l < 3) {
            k_fused<<<NB*1024, 256>>>(ww + l * 400, wb + l * NCH, src, 1);
            src ^= 1;
        } else {
            k_fused_head<<<NB*1024, 256>>>(ww + l * 400, wb + l * NCH,
                                           fc1_w, fc1_b, fc2_w, fc2_b, out, src);
        }
    }
}